// round 5
// baseline (speedup 1.0000x reference)
#include <cuda_runtime.h>
#include <cstdint>

// SpikingMLP via mma.sync.m16n8k8 TF32, with pre-split hi/lo operands.
//   rate = spike_rate(x @ w_up^T) : 3 passes (xh*uh + xh*ul + xl*uh)
//   out  = rate @ w_down^T        : 2 passes (rate*dh + rate*dl), rate tf32-exact
//   rate_per_unit = column mean of rate (exact: multiples of 1/8).

namespace cfg {
constexpr int M  = 4096;
constexpr int Dd = 1024;
constexpr int Ff = 4096;
}

// static scratch
__device__ float g_rate[(size_t)cfg::M * cfg::Ff];
__device__ float g_xh[(size_t)cfg::M * cfg::Dd];
__device__ float g_xl[(size_t)cfg::M * cfg::Dd];
__device__ float g_uh[(size_t)cfg::Ff * cfg::Dd];
__device__ float g_ul[(size_t)cfg::Ff * cfg::Dd];
__device__ float g_dh[(size_t)cfg::Dd * cfg::Ff];
__device__ float g_dl[(size_t)cfg::Dd * cfg::Ff];
__device__ float g_partial[32 * cfg::Ff];

// ------------------------------------------------------------------ helpers
__device__ __forceinline__ float f2tf32f(float f) {
    uint32_t r;
    asm("cvt.rna.tf32.f32 %0, %1;" : "=r"(r) : "f"(f));
    return __uint_as_float(r);
}
__device__ __forceinline__ void mma_tf32(float c[4],
                                         uint32_t a0, uint32_t a1, uint32_t a2, uint32_t a3,
                                         uint32_t b0, uint32_t b1) {
    asm volatile(
        "mma.sync.aligned.m16n8k8.row.col.f32.tf32.tf32.f32 "
        "{%0,%1,%2,%3}, {%4,%5,%6,%7}, {%8,%9}, {%0,%1,%2,%3};"
        : "+f"(c[0]), "+f"(c[1]), "+f"(c[2]), "+f"(c[3])
        : "r"(a0), "r"(a1), "r"(a2), "r"(a3), "r"(b0), "r"(b1));
}
__device__ __forceinline__ void cp16(uint32_t sdst, const void* gsrc) {
    asm volatile("cp.async.cg.shared.global [%0], [%1], 16;" :: "r"(sdst), "l"(gsrc));
}
#define CP_COMMIT() asm volatile("cp.async.commit_group;" ::: "memory")
#define CP_WAIT1()  asm volatile("cp.async.wait_group 1;" ::: "memory")

__device__ __forceinline__ float spike_rate_of(float h, float be, int T, float invT) {
    float v = 0.0f; int cnt = 0;
    for (int t = 0; t < T; t++) {
        v = be * v + h;
        if (v > 1.0f) { cnt++; v -= 1.0f; }
    }
    return (float)cnt * invT;
}

// ------------------------------------------------------------- split kernel
__global__ void split_kernel(const float* __restrict__ src,
                             float* __restrict__ hi, float* __restrict__ lo)
{
    const int i = blockIdx.x * 256 + threadIdx.x;      // float4 index
    float4 v = ((const float4*)src)[i];
    float4 h, l;
    h.x = f2tf32f(v.x); h.y = f2tf32f(v.y); h.z = f2tf32f(v.z); h.w = f2tf32f(v.w);
    l.x = f2tf32f(v.x - h.x); l.y = f2tf32f(v.y - h.y);
    l.z = f2tf32f(v.z - h.z); l.w = f2tf32f(v.w - h.w);
    ((float4*)hi)[i] = h;
    ((float4*)lo)[i] = l;
}

// ------------------------------------------------------------------ main GEMM
// C[128x128] per CTA. Operands pre-split, row-major [rows, KDIM] (K contiguous).
// NPASS==3: A0=Ah, A1=Al, B0=Bh, B1=Bl -> AhBh + AhBl + AlBh.
// NPASS==2: A0=A (exact),  B0=Bh, B1=Bl -> ABh + ABl.
template <int KDIM, int CH, int NPASS, bool SPIKE>
__global__ __launch_bounds__(256, 2)
void tc_gemm(const float* __restrict__ A0, const float* __restrict__ A1,
             const float* __restrict__ B0, const float* __restrict__ B1,
             float* __restrict__ C, int ldc,
             const float* __restrict__ beta, const int* __restrict__ Tptr)
{
    constexpr int LDSW   = CH + 4;
    constexpr int TILEF  = 128 * LDSW;
    constexpr int NT     = (NPASS == 3) ? 4 : 3;
    constexpr int STAGEF = NT * TILEF;
    constexpr int NC     = KDIM / CH;
    constexpr int NKS    = CH / 8;
    extern __shared__ float sm[];

    const int tid  = threadIdx.x;
    const int lane = tid & 31;
    const int wid  = tid >> 5;
    const int wm   = (wid & 1) * 64;
    const int wn   = (wid >> 1) * 32;
    const int gq   = lane >> 2;
    const int tq   = lane & 3;
    const int rowBase = blockIdx.y * 128;
    const int colBase = blockIdx.x * 128;

    // producer: 2 threads per row; each owns CH/2 floats = (CH/8) cp16 ops.
    const int prow = tid >> 1;
    const int part = (tid & 1) * (CH / 2);
    const float* gA0 = A0 + (size_t)(rowBase + prow) * KDIM + part;
    const float* gA1 = (NPASS == 3) ? A1 + (size_t)(rowBase + prow) * KDIM + part : nullptr;
    const float* gB0 = B0 + (size_t)(colBase + prow) * KDIM + part;
    const float* gB1 = B1 + (size_t)(colBase + prow) * KDIM + part;
    const uint32_t sbase = (uint32_t)__cvta_generic_to_shared(sm);
    const uint32_t pdst  = (uint32_t)(prow * LDSW + part) * 4;

    auto stage_load = [&](int c, int st) {
        const uint32_t d = sbase + (uint32_t)(st * STAGEF) * 4 + pdst;
        const int go = c * CH;
        // q < NKS: NKS cp16 x 4 floats = CH/2 floats per thread (this thread's share).
        #pragma unroll
        for (int q = 0; q < NKS; q++) {
            cp16(d + 0 * TILEF * 4 + q * 16, gA0 + go + q * 4);
            if (NPASS == 3)
                cp16(d + 1 * TILEF * 4 + q * 16, gA1 + go + q * 4);
            cp16(d + (NPASS == 3 ? 2 : 1) * TILEF * 4 + q * 16, gB0 + go + q * 4);
            cp16(d + (NPASS == 3 ? 3 : 2) * TILEF * 4 + q * 16, gB1 + go + q * 4);
        }
    };

    float acc[4][4][4];
    #pragma unroll
    for (int mi = 0; mi < 4; mi++)
        #pragma unroll
        for (int ni = 0; ni < 4; ni++)
            #pragma unroll
            for (int q = 0; q < 4; q++) acc[mi][ni][q] = 0.0f;

    stage_load(0, 0); CP_COMMIT();
    stage_load(1, 1); CP_COMMIT();

    for (int c = 0; c < NC; c++) {
        CP_WAIT1();
        __syncthreads();
        const float* s    = sm + (c & 1) * STAGEF;
        const float* ah_s = s;
        const float* al_s = s + TILEF;                          // NPASS==3 only
        const float* bh_s = s + (NPASS == 3 ? 2 : 1) * TILEF;
        const float* bl_s = bh_s + TILEF;

        #pragma unroll
        for (int ks = 0; ks < NKS; ks++) {
            const int k = ks * 8 + tq;
            uint32_t bh[4][2], bl[4][2];
            #pragma unroll
            for (int ni = 0; ni < 4; ni++) {
                const int br = wn + ni * 8 + gq;
                bh[ni][0] = __float_as_uint(bh_s[br * LDSW + k]);
                bh[ni][1] = __float_as_uint(bh_s[br * LDSW + k + 4]);
                bl[ni][0] = __float_as_uint(bl_s[br * LDSW + k]);
                bl[ni][1] = __float_as_uint(bl_s[br * LDSW + k + 4]);
            }
            #pragma unroll
            for (int mi = 0; mi < 4; mi++) {
                const int ar = wm + mi * 16 + gq;
                const uint32_t a0 = __float_as_uint(ah_s[ar * LDSW + k]);
                const uint32_t a1 = __float_as_uint(ah_s[(ar + 8) * LDSW + k]);
                const uint32_t a2 = __float_as_uint(ah_s[ar * LDSW + k + 4]);
                const uint32_t a3 = __float_as_uint(ah_s[(ar + 8) * LDSW + k + 4]);
                #pragma unroll
                for (int ni = 0; ni < 4; ni++) {
                    mma_tf32(acc[mi][ni], a0, a1, a2, a3, bh[ni][0], bh[ni][1]);
                    mma_tf32(acc[mi][ni], a0, a1, a2, a3, bl[ni][0], bl[ni][1]);
                }
                if (NPASS == 3) {
                    const uint32_t l0 = __float_as_uint(al_s[ar * LDSW + k]);
                    const uint32_t l1 = __float_as_uint(al_s[(ar + 8) * LDSW + k]);
                    const uint32_t l2 = __float_as_uint(al_s[ar * LDSW + k + 4]);
                    const uint32_t l3 = __float_as_uint(al_s[(ar + 8) * LDSW + k + 4]);
                    #pragma unroll
                    for (int ni = 0; ni < 4; ni++)
                        mma_tf32(acc[mi][ni], l0, l1, l2, l3, bh[ni][0], bh[ni][1]);
                }
            }
        }

        __syncthreads();
        if (c + 2 < NC) stage_load(c + 2, c & 1);
        CP_COMMIT();
    }

    // ---------------------------------------------------------------- epilogue
    const int T      = SPIKE ? *Tptr : 0;
    const float invT = SPIKE ? (1.0f / (float)T) : 0.0f;

    #pragma unroll
    for (int ni = 0; ni < 4; ni++) {
        const int cglob = colBase + wn + ni * 8 + 2 * tq;
        float be0 = 0.f, be1 = 0.f;
        if (SPIKE) { be0 = beta[cglob]; be1 = beta[cglob + 1]; }
        #pragma unroll
        for (int mi = 0; mi < 4; mi++) {
            const int r0 = rowBase + wm + mi * 16 + gq;
            float v00 = acc[mi][ni][0], v01 = acc[mi][ni][1];
            float v10 = acc[mi][ni][2], v11 = acc[mi][ni][3];
            if (SPIKE) {
                v00 = spike_rate_of(v00, be0, T, invT);
                v01 = spike_rate_of(v01, be1, T, invT);
                v10 = spike_rate_of(v10, be0, T, invT);
                v11 = spike_rate_of(v11, be1, T, invT);
            }
            *(float2*)(C + (size_t)r0 * ldc + cglob)       = make_float2(v00, v01);
            *(float2*)(C + (size_t)(r0 + 8) * ldc + cglob) = make_float2(v10, v11);
        }
    }
}

// ---------------------------------------------------------------- reductions
__global__ void colsum_partial_kernel()
{
    const int f  = blockIdx.x * 256 + threadIdx.x;
    const int r0 = blockIdx.y * 128;
    float s0 = 0.f, s1 = 0.f, s2 = 0.f, s3 = 0.f;
    for (int m = 0; m < 128; m += 4) {
        s0 += g_rate[(size_t)(r0 + m + 0) * cfg::Ff + f];
        s1 += g_rate[(size_t)(r0 + m + 1) * cfg::Ff + f];
        s2 += g_rate[(size_t)(r0 + m + 2) * cfg::Ff + f];
        s3 += g_rate[(size_t)(r0 + m + 3) * cfg::Ff + f];
    }
    g_partial[blockIdx.y * cfg::Ff + f] = (s0 + s1) + (s2 + s3);  // exact (k/8 sums)
}

__global__ void colsum_final_kernel(float* __restrict__ outv)
{
    const int f = blockIdx.x * 256 + threadIdx.x;
    float s = 0.f;
    #pragma unroll
    for (int b = 0; b < 32; b++) s += g_partial[b * cfg::Ff + f];
    outv[f] = s * (1.0f / (float)cfg::M);                         // /2^12: exact
}

// -------------------------------------------------------------------- launch
extern "C" void kernel_launch(void* const* d_in, const int* in_sizes, int n_in,
                              void* d_out, int out_size)
{
    const float* x      = (const float*)d_in[0];
    const float* w_up   = (const float*)d_in[1];
    const float* w_down = (const float*)d_in[2];
    const float* beta   = (const float*)d_in[3];
    const int*   Tptr   = (const int*)d_in[4];

    float* out = (float*)d_out;
    float* rpu = out + (size_t)cfg::M * cfg::Dd;

    float *rate, *xh, *xl, *uh, *ul, *dh, *dl;
    cudaGetSymbolAddress((void**)&rate, g_rate);
    cudaGetSymbolAddress((void**)&xh, g_xh);
    cudaGetSymbolAddress((void**)&xl, g_xl);
    cudaGetSymbolAddress((void**)&uh, g_uh);
    cudaGetSymbolAddress((void**)&ul, g_ul);
    cudaGetSymbolAddress((void**)&dh, g_dh);
    cudaGetSymbolAddress((void**)&dl, g_dl);

    // pre-split operands (each 4M floats -> 1M float4)
    constexpr int N4 = cfg::M * cfg::Dd / 4;
    split_kernel<<<N4 / 256, 256>>>(x, xh, xl);
    split_kernel<<<N4 / 256, 256>>>(w_up, uh, ul);
    split_kernel<<<N4 / 256, 256>>>(w_down, dh, dl);

    constexpr int SMEM1 = 2 * 4 * 128 * 20 * 4;   // 81920 B  (CH=16, 4 tiles)
    constexpr int SMEM2 = 2 * 3 * 128 * 36 * 4;   // 110592 B (CH=32, 3 tiles)
    cudaFuncSetAttribute(tc_gemm<cfg::Dd, 16, 3, true>,
                         cudaFuncAttributeMaxDynamicSharedMemorySize, SMEM1);
    cudaFuncSetAttribute(tc_gemm<cfg::Ff, 32, 2, false>,
                         cudaFuncAttributeMaxDynamicSharedMemorySize, SMEM2);

    // GEMM1 + spike epilogue -> g_rate
    tc_gemm<cfg::Dd, 16, 3, true>
        <<<dim3(cfg::Ff / 128, cfg::M / 128), 256, SMEM1>>>(
            xh, xl, uh, ul, rate, cfg::Ff, beta, Tptr);

    // per-unit firing rate
    colsum_partial_kernel<<<dim3(cfg::Ff / 256, 32), 256>>>();
    colsum_final_kernel<<<cfg::Ff / 256, 256>>>(rpu);

    // GEMM2: out = rate @ w_down^T
    tc_gemm<cfg::Ff, 32, 2, false>
        <<<dim3(cfg::Dd / 128, cfg::M / 128), 256, SMEM2>>>(
            rate, nullptr, dh, dl, out, cfg::Dd, nullptr, nullptr);
}

// round 6
// speedup vs baseline: 1.4903x; 1.4903x over previous
#include <cuda_runtime.h>
#include <cstdint>

// SpikingMLP via mma.sync.m16n8k8 TF32 with fragment-packed operands.
//   rate = spike_rate(x @ w_up^T) : 3 passes (xh*uh + xh*ul + xl*uh)
//   out  = rate @ w_down^T        : 2 passes (rate tf32-exact)
//   rate_per_unit via exact atomic column sums fused into GEMM1 epilogue.

namespace cfg {
constexpr int M  = 4096;
constexpr int Dd = 1024;
constexpr int Ff = 4096;
}

// packed scratch
__device__ float g_xh[(size_t)cfg::M * cfg::Dd];
__device__ float g_xl[(size_t)cfg::M * cfg::Dd];
__device__ float g_uh[(size_t)cfg::Ff * cfg::Dd];
__device__ float g_ul[(size_t)cfg::Ff * cfg::Dd];
__device__ float g_dh[(size_t)cfg::Dd * cfg::Ff];
__device__ float g_dl[(size_t)cfg::Dd * cfg::Ff];
__device__ float g_ratep[(size_t)cfg::M * cfg::Ff];   // GEMM2-A packed layout
__device__ float g_colsum[cfg::Ff];

// ------------------------------------------------------------------ helpers
__device__ __forceinline__ float f2tf32f(float f) {
    uint32_t r;
    asm("cvt.rna.tf32.f32 %0, %1;" : "=r"(r) : "f"(f));
    return __uint_as_float(r);
}
__device__ __forceinline__ void mma4(float c[4], const float4& a, const float2& b) {
    asm volatile(
        "mma.sync.aligned.m16n8k8.row.col.f32.tf32.tf32.f32 "
        "{%0,%1,%2,%3}, {%4,%5,%6,%7}, {%8,%9}, {%0,%1,%2,%3};"
        : "+f"(c[0]), "+f"(c[1]), "+f"(c[2]), "+f"(c[3])
        : "r"(__float_as_uint(a.x)), "r"(__float_as_uint(a.y)),
          "r"(__float_as_uint(a.z)), "r"(__float_as_uint(a.w)),
          "r"(__float_as_uint(b.x)), "r"(__float_as_uint(b.y)));
}
__device__ __forceinline__ void cp16(uint32_t sdst, const void* gsrc) {
    asm volatile("cp.async.cg.shared.global [%0], [%1], 16;" :: "r"(sdst), "l"(gsrc));
}
#define CP_COMMIT() asm volatile("cp.async.commit_group;" ::: "memory")

__device__ __forceinline__ float spike_rate_of(float h, float be, int T, float invT) {
    float v = 0.0f; int cnt = 0;
    for (int t = 0; t < T; t++) {
        v = be * v + h;
        if (v > 1.0f) { cnt++; v -= 1.0f; }
    }
    return (float)cnt * invT;
}

// -------------------------------------------------------------- pack kernels
// A [R=M, K] -> chunks [kc][mtile][rb(8)][kb(NKS)][lane(32)][4]
// fragment: {A[gq][tq], A[gq+8][tq], A[gq][tq+4], A[gq+8][tq+4]} per 16x8 block.
template <int K, int CH>
__global__ void pack_a_split(const float* __restrict__ src,
                             float* __restrict__ hi, float* __restrict__ lo)
{
    constexpr int NKS = CH / 8;
    constexpr int KB  = K / 8;
    constexpr int MT  = cfg::M / 128;
    const int wg   = (blockIdx.x * 256 + threadIdx.x) >> 5;
    const int lane = threadIdx.x & 31;
    const int rbg = wg / KB, kbg = wg % KB;
    const int gq = lane >> 2, tq = lane & 3;
    const float* s = src + (size_t)(rbg * 16) * K + kbg * 8;
    const float v0 = s[(size_t)gq * K + tq];
    const float v1 = s[(size_t)(gq + 8) * K + tq];
    const float v2 = s[(size_t)gq * K + tq + 4];
    const float v3 = s[(size_t)(gq + 8) * K + tq + 4];
    const int mtile = rbg >> 3, rb = rbg & 7, kc = kbg / NKS, kb = kbg % NKS;
    const size_t base = ((size_t)kc * MT + mtile) * (128 * CH)
                      + (size_t)(rb * NKS + kb) * 128 + lane * 4;
    float4 h, l;
    h.x = f2tf32f(v0); h.y = f2tf32f(v1); h.z = f2tf32f(v2); h.w = f2tf32f(v3);
    l.x = f2tf32f(v0 - h.x); l.y = f2tf32f(v1 - h.y);
    l.z = f2tf32f(v2 - h.z); l.w = f2tf32f(v3 - h.w);
    *(float4*)(hi + base) = h;
    *(float4*)(lo + base) = l;
}

// B [N, K] -> chunks [kc][ntile][nb(16)][kb(NKS)][lane(32)][2]
// fragment: {B[gq][tq], B[gq][tq+4]} per 8x8 block.
template <int N, int K, int CH>
__global__ void pack_b_split(const float* __restrict__ src,
                             float* __restrict__ hi, float* __restrict__ lo)
{
    constexpr int NKS = CH / 8;
    constexpr int KB  = K / 8;
    constexpr int NT  = N / 128;
    const int wg   = (blockIdx.x * 256 + threadIdx.x) >> 5;
    const int lane = threadIdx.x & 31;
    const int nbg = wg / KB, kbg = wg % KB;
    const int gq = lane >> 2, tq = lane & 3;
    const float v0 = src[(size_t)(nbg * 8 + gq) * K + kbg * 8 + tq];
    const float v1 = src[(size_t)(nbg * 8 + gq) * K + kbg * 8 + tq + 4];
    const int ntile = nbg >> 4, nb = nbg & 15, kc = kbg / NKS, kb = kbg % NKS;
    const size_t base = ((size_t)kc * NT + ntile) * (128 * CH)
                      + (size_t)(nb * NKS + kb) * 64 + lane * 2;
    float2 h, l;
    h.x = f2tf32f(v0); h.y = f2tf32f(v1);
    l.x = f2tf32f(v0 - h.x); l.y = f2tf32f(v1 - h.y);
    *(float2*)(hi + base) = h;
    *(float2*)(lo + base) = l;
}

__global__ void zero_colsum() { g_colsum[blockIdx.x * 256 + threadIdx.x] = 0.0f; }
__global__ void finalize_rpu(float* __restrict__ rpu) {
    const int f = blockIdx.x * 256 + threadIdx.x;
    rpu[f] = g_colsum[f] * (1.0f / (float)cfg::M);   // exact
}

// ------------------------------------------------------------------ main GEMM
// C-tile 128x128 per CTA; packed operands. NPASS 3: AhBh+AhBl+AlBh; 2: ABh+ABl.
template <int KDIM, int CH, int NPASS, bool SPIKE, int STAGES, int NTB>
__global__ __launch_bounds__(256, 2)
void tc_gemm(const float* __restrict__ A0, const float* __restrict__ A1,
             const float* __restrict__ B0, const float* __restrict__ B1,
             float* __restrict__ C,
             const float* __restrict__ beta, const int* __restrict__ Tptr)
{
    constexpr int TA     = 128 * CH;                 // floats per tile
    constexpr int NT     = (NPASS == 3) ? 4 : 3;
    constexpr int STAGEF = NT * TA;
    constexpr int NC     = KDIM / CH;
    constexpr int NKS    = CH / 8;
    constexpr int F4     = TA / 1024;                // float4 per thread per tile
    extern __shared__ float sm[];

    const int tid = threadIdx.x, lane = tid & 31, wid = tid >> 5;
    const int gq = lane >> 2, tq = lane & 3;
    const int mtile = blockIdx.y, ntile = blockIdx.x;
    const int rowBase = mtile * 128, colBase = ntile * 128;
    const int rbb = (wid & 1) * 4, nbb = (wid >> 1) * 4;
    const int wm = (wid & 1) * 64, wn = (wid >> 1) * 32;

    const uint32_t sb = (uint32_t)__cvta_generic_to_shared(sm);

    const float4* pA0 = (const float4*)A0 + (size_t)mtile * (TA / 4);
    const float4* pA1 = (NPASS == 3) ? (const float4*)A1 + (size_t)mtile * (TA / 4) : nullptr;
    const float4* pB0 = (const float4*)B0 + (size_t)ntile * (TA / 4);
    const float4* pB1 = (const float4*)B1 + (size_t)ntile * (TA / 4);
    constexpr size_t strideA4 = (size_t)(cfg::M / 128) * (TA / 4);
    constexpr size_t strideB4 = (size_t)NTB * (TA / 4);

    auto stage_load = [&](int c, int st) {
        const uint32_t d = sb + (uint32_t)st * STAGEF * 4;
        const float4* a0 = pA0 + (size_t)c * strideA4;
        const float4* a1 = (NPASS == 3) ? pA1 + (size_t)c * strideA4 : nullptr;
        const float4* b0 = pB0 + (size_t)c * strideB4;
        const float4* b1 = pB1 + (size_t)c * strideB4;
        #pragma unroll
        for (int q = 0; q < F4; q++) {
            const int idx = q * 256 + tid;
            cp16(d + idx * 16, a0 + idx);
            if (NPASS == 3)
                cp16(d + (uint32_t)TA * 4 + idx * 16, a1 + idx);
            cp16(d + (uint32_t)((NPASS == 3 ? 2 : 1) * TA) * 4 + idx * 16, b0 + idx);
            cp16(d + (uint32_t)((NPASS == 3 ? 3 : 2) * TA) * 4 + idx * 16, b1 + idx);
        }
    };

    float acc[4][4][4];
    #pragma unroll
    for (int mi = 0; mi < 4; mi++)
        #pragma unroll
        for (int ni = 0; ni < 4; ni++)
            #pragma unroll
            for (int q = 0; q < 4; q++) acc[mi][ni][q] = 0.0f;

    #pragma unroll
    for (int s = 0; s < STAGES; s++) { stage_load(s, s); CP_COMMIT(); }

    int st = 0;
    for (int c = 0; c < NC; c++) {
        if constexpr (STAGES == 3)
            asm volatile("cp.async.wait_group 2;" ::: "memory");
        else
            asm volatile("cp.async.wait_group 1;" ::: "memory");
        __syncthreads();
        const float* s0  = sm + st * STAGEF;
        const float* ahs = s0;
        const float* als = s0 + TA;
        const float* bhs = s0 + (NPASS == 3 ? 2 : 1) * TA;
        const float* bls = bhs + TA;

        #pragma unroll
        for (int ks = 0; ks < NKS; ks++) {
            float2 bh[4], bl[4];
            #pragma unroll
            for (int ni = 0; ni < 4; ni++) {
                bh[ni] = *(const float2*)(bhs + ((nbb + ni) * NKS + ks) * 64 + lane * 2);
                bl[ni] = *(const float2*)(bls + ((nbb + ni) * NKS + ks) * 64 + lane * 2);
            }
            #pragma unroll
            for (int mp = 0; mp < 2; mp++) {
                const int m0 = 2 * mp, m1 = 2 * mp + 1;
                const float4 a0 = *(const float4*)(ahs + ((rbb + m0) * NKS + ks) * 128 + lane * 4);
                const float4 a1 = *(const float4*)(ahs + ((rbb + m1) * NKS + ks) * 128 + lane * 4);
                #pragma unroll
                for (int ni = 0; ni < 4; ni++) mma4(acc[m0][ni], a0, bh[ni]);
                #pragma unroll
                for (int ni = 0; ni < 4; ni++) mma4(acc[m1][ni], a1, bh[ni]);
                #pragma unroll
                for (int ni = 0; ni < 4; ni++) mma4(acc[m0][ni], a0, bl[ni]);
                #pragma unroll
                for (int ni = 0; ni < 4; ni++) mma4(acc[m1][ni], a1, bl[ni]);
                if (NPASS == 3) {
                    const float4 l0 = *(const float4*)(als + ((rbb + m0) * NKS + ks) * 128 + lane * 4);
                    const float4 l1 = *(const float4*)(als + ((rbb + m1) * NKS + ks) * 128 + lane * 4);
                    #pragma unroll
                    for (int ni = 0; ni < 4; ni++) mma4(acc[m0][ni], l0, bh[ni]);
                    #pragma unroll
                    for (int ni = 0; ni < 4; ni++) mma4(acc[m1][ni], l1, bh[ni]);
                }
            }
        }
        __syncthreads();
        if (c + STAGES < NC) stage_load(c + STAGES, st);
        CP_COMMIT();
        st = (st + 1 == STAGES) ? 0 : st + 1;
    }

    // ---------------------------------------------------------------- epilogue
    if constexpr (SPIKE) {
        const int   T    = *Tptr;
        const float invT = 1.0f / (float)T;
        // stage rate tile in smem (stride 132 -> conflict-free col sums & frag reads)
        #pragma unroll
        for (int ni = 0; ni < 4; ni++) {
            const int cl = wn + ni * 8 + 2 * tq;
            const float be0 = beta[colBase + cl];
            const float be1 = beta[colBase + cl + 1];
            #pragma unroll
            for (int mi = 0; mi < 4; mi++) {
                const int r0 = wm + mi * 16 + gq;
                sm[r0 * 132 + cl]           = spike_rate_of(acc[mi][ni][0], be0, T, invT);
                sm[r0 * 132 + cl + 1]       = spike_rate_of(acc[mi][ni][1], be1, T, invT);
                sm[(r0 + 8) * 132 + cl]     = spike_rate_of(acc[mi][ni][2], be0, T, invT);
                sm[(r0 + 8) * 132 + cl + 1] = spike_rate_of(acc[mi][ni][3], be1, T, invT);
            }
        }
        __syncthreads();
        // exact column sums (multiples of 1/8 -> atomic order irrelevant)
        if (tid < 128) {
            float s = 0.0f;
            #pragma unroll 8
            for (int r = 0; r < 128; r++) s += sm[r * 132 + tid];
            atomicAdd(&g_colsum[colBase + tid], s);
        }
        // write rate in GEMM2 packed-A layout (CH2=32, NKS2=4, MT=32)
        #pragma unroll
        for (int i = 0; i < 16; i++) {
            const int idx = i * 256 + tid;            // 0..4095 float4s
            const int l2  = idx & 31;
            const int t2  = idx >> 5;                 // kcj*32 + rb*4 + kb
            const int kcj = t2 >> 5;
            const int pos = t2 & 31;                  // rb*4+kb
            const int g2 = l2 >> 2, q2 = l2 & 3;
            const int ml = (pos >> 2) * 16;
            const int fl = kcj * 32 + (pos & 3) * 8;
            float4 v;
            v.x = sm[(ml + g2) * 132 + fl + q2];
            v.y = sm[(ml + g2 + 8) * 132 + fl + q2];
            v.z = sm[(ml + g2) * 132 + fl + q2 + 4];
            v.w = sm[(ml + g2 + 8) * 132 + fl + q2 + 4];
            const size_t cb4 = ((size_t)(colBase / 32 + kcj) * 32 + mtile) * 1024;
            ((float4*)g_ratep)[cb4 + pos * 32 + l2] = v;
        }
    } else {
        #pragma unroll
        for (int ni = 0; ni < 4; ni++) {
            const int cglob = colBase + wn + ni * 8 + 2 * tq;
            #pragma unroll
            for (int mi = 0; mi < 4; mi++) {
                const int r0 = rowBase + wm + mi * 16 + gq;
                *(float2*)(C + (size_t)r0 * cfg::Dd + cglob) =
                    make_float2(acc[mi][ni][0], acc[mi][ni][1]);
                *(float2*)(C + (size_t)(r0 + 8) * cfg::Dd + cglob) =
                    make_float2(acc[mi][ni][2], acc[mi][ni][3]);
            }
        }
    }
}

// -------------------------------------------------------------------- launch
extern "C" void kernel_launch(void* const* d_in, const int* in_sizes, int n_in,
                              void* d_out, int out_size)
{
    const float* x      = (const float*)d_in[0];
    const float* w_up   = (const float*)d_in[1];
    const float* w_down = (const float*)d_in[2];
    const float* beta   = (const float*)d_in[3];
    const int*   Tptr   = (const int*)d_in[4];

    float* out = (float*)d_out;
    float* rpu = out + (size_t)cfg::M * cfg::Dd;

    float *xh, *xl, *uh, *ul, *dh, *dl, *ratep;
    cudaGetSymbolAddress((void**)&xh, g_xh);
    cudaGetSymbolAddress((void**)&xl, g_xl);
    cudaGetSymbolAddress((void**)&uh, g_uh);
    cudaGetSymbolAddress((void**)&ul, g_ul);
    cudaGetSymbolAddress((void**)&dh, g_dh);
    cudaGetSymbolAddress((void**)&dl, g_dl);
    cudaGetSymbolAddress((void**)&ratep, g_ratep);

    zero_colsum<<<cfg::Ff / 256, 256>>>();
    // x: A of GEMM1 (K=1024, CH=16): (4096/16)*(1024/8)=32768 warps
    pack_a_split<1024, 16><<<4096, 256>>>(x, xh, xl);
    // w_up: B of GEMM1 (N=4096, K=1024, CH=16): 512*128=65536 warps
    pack_b_split<4096, 1024, 16><<<8192, 256>>>(w_up, uh, ul);
    // w_down: B of GEMM2 (N=1024, K=4096, CH=32): 128*512=65536 warps
    pack_b_split<1024, 4096, 32><<<8192, 256>>>(w_down, dh, dl);

    constexpr int SMEM = 3 * 4 * 128 * 16 * 4;   // 98304 B (also = 2*3*128*32*4)
    cudaFuncSetAttribute(tc_gemm<1024, 16, 3, true, 3, 32>,
                         cudaFuncAttributeMaxDynamicSharedMemorySize, SMEM);
    cudaFuncSetAttribute(tc_gemm<4096, 32, 2, false, 2, 8>,
                         cudaFuncAttributeMaxDynamicSharedMemorySize, SMEM);

    // GEMM1 + spike + colsum + packed-rate epilogue
    tc_gemm<1024, 16, 3, true, 3, 32>
        <<<dim3(cfg::Ff / 128, cfg::M / 128), 256, SMEM>>>(
            xh, xl, uh, ul, nullptr, beta, Tptr);

    finalize_rpu<<<cfg::Ff / 256, 256>>>(rpu);

    // GEMM2: out = rate @ w_down^T
    tc_gemm<4096, 32, 2, false, 2, 8>
        <<<dim3(cfg::Dd / 128, cfg::M / 128), 256, SMEM>>>(
            ratep, nullptr, dh, dl, out, nullptr, nullptr);
}

// round 7
// speedup vs baseline: 1.6923x; 1.1356x over previous
#include <cuda_runtime.h>
#include <cuda_bf16.h>
#include <cstdint>

// SpikingMLP:
//   GEMM1 (tf32 3-pass, bit-identical to R6): rate = spike_rate(x @ w_up^T)
//   GEMM2 (bf16 m16n8k16, 2-term split of w_down): out = rate @ w_down^T
//   rate is exact in bf16 (multiples of 1/8) -> GEMM2 A needs no split.
//   rate_per_unit via exact atomic column sums in GEMM1 epilogue.

namespace cfg {
constexpr int M  = 4096;
constexpr int Dd = 1024;
constexpr int Ff = 4096;
}

// packed scratch
__device__ float g_xh[(size_t)cfg::M * cfg::Dd];
__device__ float g_xl[(size_t)cfg::M * cfg::Dd];
__device__ float g_uh[(size_t)cfg::Ff * cfg::Dd];
__device__ float g_ul[(size_t)cfg::Ff * cfg::Dd];
__device__ uint4 g_dh[(size_t)cfg::Dd * cfg::Ff / 8];     // bf16, fragment-packed
__device__ uint4 g_dl[(size_t)cfg::Dd * cfg::Ff / 8];
__device__ uint4 g_ratep[(size_t)cfg::M * cfg::Ff / 8];   // rate as bf16, GEMM2-A packed
__device__ float g_colsum[cfg::Ff];

// ------------------------------------------------------------------ helpers
__device__ __forceinline__ float f2tf32f(float f) {
    uint32_t r;
    asm("cvt.rna.tf32.f32 %0, %1;" : "=r"(r) : "f"(f));
    return __uint_as_float(r);
}
__device__ __forceinline__ uint32_t pack_bf2(float lo, float hi) {
    __nv_bfloat162 p = __floats2bfloat162_rn(lo, hi);   // .x = lo (low half)
    return *(uint32_t*)&p;
}
__device__ __forceinline__ void mma4(float c[4], const float4& a, const float2& b) {
    asm volatile(
        "mma.sync.aligned.m16n8k8.row.col.f32.tf32.tf32.f32 "
        "{%0,%1,%2,%3}, {%4,%5,%6,%7}, {%8,%9}, {%0,%1,%2,%3};"
        : "+f"(c[0]), "+f"(c[1]), "+f"(c[2]), "+f"(c[3])
        : "r"(__float_as_uint(a.x)), "r"(__float_as_uint(a.y)),
          "r"(__float_as_uint(a.z)), "r"(__float_as_uint(a.w)),
          "r"(__float_as_uint(b.x)), "r"(__float_as_uint(b.y)));
}
__device__ __forceinline__ void mma_bf16(float c[4], const uint4& a, const uint2& b) {
    asm volatile(
        "mma.sync.aligned.m16n8k16.row.col.f32.bf16.bf16.f32 "
        "{%0,%1,%2,%3}, {%4,%5,%6,%7}, {%8,%9}, {%0,%1,%2,%3};"
        : "+f"(c[0]), "+f"(c[1]), "+f"(c[2]), "+f"(c[3])
        : "r"(a.x), "r"(a.y), "r"(a.z), "r"(a.w), "r"(b.x), "r"(b.y));
}
__device__ __forceinline__ void cp16(uint32_t sdst, const void* gsrc) {
    asm volatile("cp.async.cg.shared.global [%0], [%1], 16;" :: "r"(sdst), "l"(gsrc));
}
#define CP_COMMIT() asm volatile("cp.async.commit_group;" ::: "memory")

__device__ __forceinline__ float spike_rate_of(float h, float be, int T, float invT) {
    float v = 0.0f; int cnt = 0;
    for (int t = 0; t < T; t++) {
        v = be * v + h;
        if (v > 1.0f) { cnt++; v -= 1.0f; }
    }
    return (float)cnt * invT;
}

// -------------------------------------------------------------- pack kernels
// A [M, K=1024] -> tf32 hi/lo chunks [kc][mtile][rb(8)][kb(2)][lane(32)][4]
__global__ void pack_a_split(const float* __restrict__ src,
                             float* __restrict__ hi, float* __restrict__ lo)
{
    constexpr int K = 1024, CH = 16, NKS = CH / 8, KB = K / 8, MT = cfg::M / 128;
    const int wg   = (blockIdx.x * 256 + threadIdx.x) >> 5;
    const int lane = threadIdx.x & 31;
    const int rbg = wg / KB, kbg = wg % KB;
    const int gq = lane >> 2, tq = lane & 3;
    const float* s = src + (size_t)(rbg * 16) * K + kbg * 8;
    const float v0 = s[(size_t)gq * K + tq];
    const float v1 = s[(size_t)(gq + 8) * K + tq];
    const float v2 = s[(size_t)gq * K + tq + 4];
    const float v3 = s[(size_t)(gq + 8) * K + tq + 4];
    const int mtile = rbg >> 3, rb = rbg & 7, kc = kbg / NKS, kb = kbg % NKS;
    const size_t base = ((size_t)kc * MT + mtile) * (128 * CH)
                      + (size_t)(rb * NKS + kb) * 128 + lane * 4;
    float4 h, l;
    h.x = f2tf32f(v0); h.y = f2tf32f(v1); h.z = f2tf32f(v2); h.w = f2tf32f(v3);
    l.x = f2tf32f(v0 - h.x); l.y = f2tf32f(v1 - h.y);
    l.z = f2tf32f(v2 - h.z); l.w = f2tf32f(v3 - h.w);
    *(float4*)(hi + base) = h;
    *(float4*)(lo + base) = l;
}

// B [N=4096, K=1024] -> tf32 hi/lo chunks [kc][ntile][nb(16)][kb(2)][lane(32)][2]
__global__ void pack_b_split(const float* __restrict__ src,
                             float* __restrict__ hi, float* __restrict__ lo)
{
    constexpr int N = 4096, K = 1024, CH = 16, NKS = CH / 8, KB = K / 8, NT = N / 128;
    const int wg   = (blockIdx.x * 256 + threadIdx.x) >> 5;
    const int lane = threadIdx.x & 31;
    const int nbg = wg / KB, kbg = wg % KB;
    const int gq = lane >> 2, tq = lane & 3;
    const float v0 = src[(size_t)(nbg * 8 + gq) * K + kbg * 8 + tq];
    const float v1 = src[(size_t)(nbg * 8 + gq) * K + kbg * 8 + tq + 4];
    const int ntile = nbg >> 4, nb = nbg & 15, kc = kbg / NKS, kb = kbg % NKS;
    const size_t base = ((size_t)kc * NT + ntile) * (128 * CH)
                      + (size_t)(nb * NKS + kb) * 64 + lane * 2;
    float2 h, l;
    h.x = f2tf32f(v0); h.y = f2tf32f(v1);
    l.x = f2tf32f(v0 - h.x); l.y = f2tf32f(v1 - h.y);
    *(float2*)(hi + base) = h;
    *(float2*)(lo + base) = l;
}

// w_down [N=1024, K=4096] -> bf16 hi/lo, GEMM2-B layout
// [kc(64)][ntile(8)][nb(16)][kb(4)][lane(32)][uint2 = 4 bf16]
__global__ void pack_b_bf16(const float* __restrict__ src,
                            uint2* __restrict__ hi, uint2* __restrict__ lo)
{
    constexpr int K = 4096, KB16 = K / 16;
    const int wg   = (blockIdx.x * 256 + threadIdx.x) >> 5;
    const int lane = threadIdx.x & 31;
    const int nbg = wg / KB16, kbg = wg % KB16;
    const int gq = lane >> 2, tq = lane & 3;
    const float* s = src + (size_t)(nbg * 8 + gq) * K + kbg * 16;
    const float v0 = s[2 * tq], v1 = s[2 * tq + 1];
    const float v2 = s[2 * tq + 8], v3 = s[2 * tq + 9];
    const float h0 = __bfloat162float(__float2bfloat16_rn(v0));
    const float h1 = __bfloat162float(__float2bfloat16_rn(v1));
    const float h2 = __bfloat162float(__float2bfloat16_rn(v2));
    const float h3 = __bfloat162float(__float2bfloat16_rn(v3));
    const int ntile = nbg >> 4, nb = nbg & 15, kc = kbg >> 2, kb = kbg & 3;
    const size_t idx = ((((size_t)kc * 8 + ntile) * 16 + nb) * 4 + kb) * 32 + lane;
    hi[idx] = make_uint2(pack_bf2(h0, h1), pack_bf2(h2, h3));
    lo[idx] = make_uint2(pack_bf2(v0 - h0, v1 - h1), pack_bf2(v2 - h2, v3 - h3));
}

__global__ void zero_colsum() { g_colsum[blockIdx.x * 256 + threadIdx.x] = 0.0f; }
__global__ void finalize_rpu(float* __restrict__ rpu) {
    const int f = blockIdx.x * 256 + threadIdx.x;
    rpu[f] = g_colsum[f] * (1.0f / (float)cfg::M);   // exact
}

// --------------------------------------------------- GEMM1 (tf32, 3 passes)
// identical math/order to R6 (bit-identical h/rate); epilogue emits bf16 ratep.
__global__ __launch_bounds__(256, 2)
void tc_gemm1(const float* __restrict__ A0, const float* __restrict__ A1,
              const float* __restrict__ B0, const float* __restrict__ B1,
              const float* __restrict__ beta, const int* __restrict__ Tptr)
{
    constexpr int CH = 16, TA = 128 * CH, STAGEF = 4 * TA;
    constexpr int NC = cfg::Dd / CH, NKS = CH / 8, STAGES = 3;
    extern __shared__ float sm[];

    const int tid = threadIdx.x, lane = tid & 31, wid = tid >> 5;
    const int gq = lane >> 2, tq = lane & 3;
    const int mtile = blockIdx.y, ntile = blockIdx.x;
    const int colBase = ntile * 128;
    const int rbb = (wid & 1) * 4, nbb = (wid >> 1) * 4;
    const int wm = (wid & 1) * 64, wn = (wid >> 1) * 32;
    const uint32_t sb = (uint32_t)__cvta_generic_to_shared(sm);

    const float4* pA0 = (const float4*)A0 + (size_t)mtile * (TA / 4);
    const float4* pA1 = (const float4*)A1 + (size_t)mtile * (TA / 4);
    const float4* pB0 = (const float4*)B0 + (size_t)ntile * (TA / 4);
    const float4* pB1 = (const float4*)B1 + (size_t)ntile * (TA / 4);
    constexpr size_t strideA4 = (size_t)(cfg::M / 128) * (TA / 4);
    constexpr size_t strideB4 = (size_t)(cfg::Ff / 128) * (TA / 4);

    auto stage_load = [&](int c, int st) {
        const uint32_t d = sb + (uint32_t)st * STAGEF * 4;
        const float4* a0 = pA0 + (size_t)c * strideA4;
        const float4* a1 = pA1 + (size_t)c * strideA4;
        const float4* b0 = pB0 + (size_t)c * strideB4;
        const float4* b1 = pB1 + (size_t)c * strideB4;
        #pragma unroll
        for (int q = 0; q < TA / 1024; q++) {
            const int idx = q * 256 + tid;
            cp16(d + idx * 16, a0 + idx);
            cp16(d + (uint32_t)TA * 4 + idx * 16, a1 + idx);
            cp16(d + (uint32_t)(2 * TA) * 4 + idx * 16, b0 + idx);
            cp16(d + (uint32_t)(3 * TA) * 4 + idx * 16, b1 + idx);
        }
    };

    float acc[4][4][4];
    #pragma unroll
    for (int mi = 0; mi < 4; mi++)
        #pragma unroll
        for (int ni = 0; ni < 4; ni++)
            #pragma unroll
            for (int q = 0; q < 4; q++) acc[mi][ni][q] = 0.0f;

    #pragma unroll
    for (int s = 0; s < STAGES; s++) { stage_load(s, s); CP_COMMIT(); }

    int st = 0;
    for (int c = 0; c < NC; c++) {
        asm volatile("cp.async.wait_group 2;" ::: "memory");
        __syncthreads();
        const float* s0  = sm + st * STAGEF;
        const float* ahs = s0;
        const float* als = s0 + TA;
        const float* bhs = s0 + 2 * TA;
        const float* bls = s0 + 3 * TA;

        #pragma unroll
        for (int ks = 0; ks < NKS; ks++) {
            float2 bh[4], bl[4];
            #pragma unroll
            for (int ni = 0; ni < 4; ni++) {
                bh[ni] = *(const float2*)(bhs + ((nbb + ni) * NKS + ks) * 64 + lane * 2);
                bl[ni] = *(const float2*)(bls + ((nbb + ni) * NKS + ks) * 64 + lane * 2);
            }
            #pragma unroll
            for (int mp = 0; mp < 2; mp++) {
                const int m0 = 2 * mp, m1 = 2 * mp + 1;
                const float4 a0 = *(const float4*)(ahs + ((rbb + m0) * NKS + ks) * 128 + lane * 4);
                const float4 a1 = *(const float4*)(ahs + ((rbb + m1) * NKS + ks) * 128 + lane * 4);
                #pragma unroll
                for (int ni = 0; ni < 4; ni++) mma4(acc[m0][ni], a0, bh[ni]);
                #pragma unroll
                for (int ni = 0; ni < 4; ni++) mma4(acc[m1][ni], a1, bh[ni]);
                #pragma unroll
                for (int ni = 0; ni < 4; ni++) mma4(acc[m0][ni], a0, bl[ni]);
                #pragma unroll
                for (int ni = 0; ni < 4; ni++) mma4(acc[m1][ni], a1, bl[ni]);
                const float4 l0 = *(const float4*)(als + ((rbb + m0) * NKS + ks) * 128 + lane * 4);
                const float4 l1 = *(const float4*)(als + ((rbb + m1) * NKS + ks) * 128 + lane * 4);
                #pragma unroll
                for (int ni = 0; ni < 4; ni++) mma4(acc[m0][ni], l0, bh[ni]);
                #pragma unroll
                for (int ni = 0; ni < 4; ni++) mma4(acc[m1][ni], l1, bh[ni]);
            }
        }
        __syncthreads();
        if (c + STAGES < NC) stage_load(c + STAGES, st);
        CP_COMMIT();
        st = (st + 1 == STAGES) ? 0 : st + 1;
    }

    // epilogue: spike -> stage rate tile (f32, stride 132) -> colsum + bf16 ratep
    const int   T    = *Tptr;
    const float invT = 1.0f / (float)T;
    #pragma unroll
    for (int ni = 0; ni < 4; ni++) {
        const int cl = wn + ni * 8 + 2 * tq;
        const float be0 = beta[colBase + cl];
        const float be1 = beta[colBase + cl + 1];
        #pragma unroll
        for (int mi = 0; mi < 4; mi++) {
            const int r0 = wm + mi * 16 + gq;
            sm[r0 * 132 + cl]           = spike_rate_of(acc[mi][ni][0], be0, T, invT);
            sm[r0 * 132 + cl + 1]       = spike_rate_of(acc[mi][ni][1], be1, T, invT);
            sm[(r0 + 8) * 132 + cl]     = spike_rate_of(acc[mi][ni][2], be0, T, invT);
            sm[(r0 + 8) * 132 + cl + 1] = spike_rate_of(acc[mi][ni][3], be1, T, invT);
        }
    }
    __syncthreads();
    if (tid < 128) {
        float s = 0.0f;
        #pragma unroll 8
        for (int r = 0; r < 128; r++) s += sm[r * 132 + tid];
        atomicAdd(&g_colsum[colBase + tid], s);   // exact: multiples of 1/8
    }
    // write rate (exact bf16) in GEMM2-A packed layout:
    // [kc2(F/64)][mtile(32)][rb(8)][kb2(4)][lane(32)][uint4 = 8 bf16]
    #pragma unroll
    for (int i = 0; i < 8; i++) {
        const int idx = i * 256 + tid;           // 0..2047 uint4s
        const int l2  = idx & 31;
        const int t2  = idx >> 5;                // 0..63
        const int kcj = t2 >> 5;                 // 0..1
        const int pos = t2 & 31;                 // rb*4+kb2
        const int g2 = l2 >> 2, q2 = l2 & 3;
        const int ml = (pos >> 2) * 16;
        const int fl = kcj * 64 + (pos & 3) * 16;
        const int ra = ml + g2, rb2 = ml + g2 + 8;
        const int c0 = fl + 2 * q2, c8 = fl + 2 * q2 + 8;
        uint4 v;
        v.x = pack_bf2(sm[ra * 132 + c0],  sm[ra * 132 + c0 + 1]);
        v.y = pack_bf2(sm[rb2 * 132 + c0], sm[rb2 * 132 + c0 + 1]);
        v.z = pack_bf2(sm[ra * 132 + c8],  sm[ra * 132 + c8 + 1]);
        v.w = pack_bf2(sm[rb2 * 132 + c8], sm[rb2 * 132 + c8 + 1]);
        g_ratep[((size_t)(colBase / 64 + kcj) * 32 + mtile) * 1024 + pos * 32 + l2] = v;
    }
}

// --------------------------------------------- GEMM2 (bf16 m16n8k16, 2 pass)
// out[M, Dd] = rate @ w_down^T.  A = g_ratep (exact bf16), B = dh + dl.
__global__ __launch_bounds__(256, 2)
void tc_gemm2(const uint4* __restrict__ A, const uint4* __restrict__ Bh,
              const uint4* __restrict__ Bl, float* __restrict__ C)
{
    constexpr int CH = 64;                       // K floats per chunk
    constexpr int TILE = 16384;                  // bytes per tile (A or B)
    constexpr int STAGE = 3 * TILE;              // A + Bh + Bl
    constexpr int NC = cfg::Ff / CH;             // 64
    extern __shared__ char smc[];

    const int tid = threadIdx.x, lane = tid & 31, wid = tid >> 5;
    const int gq = lane >> 2, tq = lane & 3;
    const int mtile = blockIdx.y, ntile = blockIdx.x;
    const int rowBase = mtile * 128, colBase = ntile * 128;
    const int rbb = (wid & 1) * 4, nbb = (wid >> 1) * 4;
    const int wm = (wid & 1) * 64, wn = (wid >> 1) * 32;
    const uint32_t sb = (uint32_t)__cvta_generic_to_shared(smc);

    const uint4* pA  = A  + (size_t)mtile * 1024;   // tile = 1024 uint4
    const uint4* pBh = Bh + (size_t)ntile * 1024;
    const uint4* pBl = Bl + (size_t)ntile * 1024;
    constexpr size_t strideA = (size_t)32 * 1024;   // MT * tile
    constexpr size_t strideB = (size_t)8 * 1024;    // NT * tile

    auto stage_load = [&](int c, int st) {
        const uint32_t d = sb + (uint32_t)st * STAGE;
        const uint4* a  = pA  + (size_t)c * strideA;
        const uint4* b0 = pBh + (size_t)c * strideB;
        const uint4* b1 = pBl + (size_t)c * strideB;
        #pragma unroll
        for (int q = 0; q < 4; q++) {
            const int idx = q * 256 + tid;
            cp16(d + idx * 16, a + idx);
            cp16(d + TILE + idx * 16, b0 + idx);
            cp16(d + 2 * TILE + idx * 16, b1 + idx);
        }
    };

    float acc[4][4][4];
    #pragma unroll
    for (int mi = 0; mi < 4; mi++)
        #pragma unroll
        for (int ni = 0; ni < 4; ni++)
            #pragma unroll
            for (int q = 0; q < 4; q++) acc[mi][ni][q] = 0.0f;

    stage_load(0, 0); CP_COMMIT();
    stage_load(1, 1); CP_COMMIT();

    int st = 0;
    for (int c = 0; c < NC; c++) {
        asm volatile("cp.async.wait_group 1;" ::: "memory");
        __syncthreads();
        const uint4* ahs = (const uint4*)(smc + st * STAGE);
        const uint2* bhs = (const uint2*)(smc + st * STAGE + TILE);
        const uint2* bls = (const uint2*)(smc + st * STAGE + 2 * TILE);

        #pragma unroll
        for (int ks = 0; ks < 4; ks++) {
            uint2 bh[4], bl[4];
            #pragma unroll
            for (int ni = 0; ni < 4; ni++) {
                bh[ni] = bhs[((nbb + ni) * 4 + ks) * 32 + lane];
                bl[ni] = bls[((nbb + ni) * 4 + ks) * 32 + lane];
            }
            #pragma unroll
            for (int mp = 0; mp < 2; mp++) {
                const int m0 = 2 * mp, m1 = 2 * mp + 1;
                const uint4 a0 = ahs[((rbb + m0) * 4 + ks) * 32 + lane];
                const uint4 a1 = ahs[((rbb + m1) * 4 + ks) * 32 + lane];
                #pragma unroll
                for (int ni = 0; ni < 4; ni++) mma_bf16(acc[m0][ni], a0, bh[ni]);
                #pragma unroll
                for (int ni = 0; ni < 4; ni++) mma_bf16(acc[m1][ni], a1, bh[ni]);
                #pragma unroll
                for (int ni = 0; ni < 4; ni++) mma_bf16(acc[m0][ni], a0, bl[ni]);
                #pragma unroll
                for (int ni = 0; ni < 4; ni++) mma_bf16(acc[m1][ni], a1, bl[ni]);
            }
        }
        __syncthreads();
        if (c + 2 < NC) stage_load(c + 2, st);
        CP_COMMIT();
        st ^= 1;
    }

    #pragma unroll
    for (int ni = 0; ni < 4; ni++) {
        const int cglob = colBase + wn + ni * 8 + 2 * tq;
        #pragma unroll
        for (int mi = 0; mi < 4; mi++) {
            const int r0 = rowBase + wm + mi * 16 + gq;
            *(float2*)(C + (size_t)r0 * cfg::Dd + cglob) =
                make_float2(acc[mi][ni][0], acc[mi][ni][1]);
            *(float2*)(C + (size_t)(r0 + 8) * cfg::Dd + cglob) =
                make_float2(acc[mi][ni][2], acc[mi][ni][3]);
        }
    }
}

// -------------------------------------------------------------------- launch
extern "C" void kernel_launch(void* const* d_in, const int* in_sizes, int n_in,
                              void* d_out, int out_size)
{
    const float* x      = (const float*)d_in[0];
    const float* w_up   = (const float*)d_in[1];
    const float* w_down = (const float*)d_in[2];
    const float* beta   = (const float*)d_in[3];
    const int*   Tptr   = (const int*)d_in[4];

    float* out = (float*)d_out;
    float* rpu = out + (size_t)cfg::M * cfg::Dd;

    float *xh, *xl, *uh, *ul;
    uint4 *dh, *dl, *ratep;
    cudaGetSymbolAddress((void**)&xh, g_xh);
    cudaGetSymbolAddress((void**)&xl, g_xl);
    cudaGetSymbolAddress((void**)&uh, g_uh);
    cudaGetSymbolAddress((void**)&ul, g_ul);
    cudaGetSymbolAddress((void**)&dh, g_dh);
    cudaGetSymbolAddress((void**)&dl, g_dl);
    cudaGetSymbolAddress((void**)&ratep, g_ratep);

    zero_colsum<<<cfg::Ff / 256, 256>>>();
    pack_a_split<<<4096, 256>>>(x, xh, xl);                          // 32768 warps
    pack_b_split<<<8192, 256>>>(w_up, uh, ul);                       // 65536 warps
    pack_b_bf16<<<4096, 256>>>(w_down, (uint2*)dh, (uint2*)dl);      // 32768 warps

    constexpr int SMEM1 = 3 * 4 * 128 * 16 * 4;   // 98304 B
    constexpr int SMEM2 = 2 * 3 * 16384;          // 98304 B
    cudaFuncSetAttribute(tc_gemm1, cudaFuncAttributeMaxDynamicSharedMemorySize, SMEM1);
    cudaFuncSetAttribute(tc_gemm2, cudaFuncAttributeMaxDynamicSharedMemorySize, SMEM2);

    tc_gemm1<<<dim3(cfg::Ff / 128, cfg::M / 128), 256, SMEM1>>>(
        xh, xl, uh, ul, beta, Tptr);

    finalize_rpu<<<cfg::Ff / 256, 256>>>(rpu);

    tc_gemm2<<<dim3(cfg::Dd / 128, cfg::M / 128), 256, SMEM2>>>(
        ratep, dh, dl, out);
}

// round 8
// speedup vs baseline: 2.7361x; 1.6167x over previous
#include <cuda_runtime.h>
#include <cuda_bf16.h>
#include <cuda_fp16.h>
#include <cstdint>

// SpikingMLP:
//   GEMM1 (fp16 m16n8k16 3-pass, w_up scaled by 2^8): rate = spike_rate(x @ w_up^T)
//   GEMM2 (bf16 m16n8k16 2-pass, identical to R7):    out  = rate @ w_down^T
//   rate_per_unit via exact atomic column sums in GEMM1 epilogue.

namespace cfg {
constexpr int M  = 4096;
constexpr int Dd = 1024;
constexpr int Ff = 4096;
}

// GEMM1 fp16 packed operands: A [kc(32)][mtile(32)][rb(8)][kb(2)][lane(32)] uint4
//                             B [kc(32)][ntile(32)][nb(16)][kb(2)][lane(32)] uint2
__device__ uint4 g_axh[(size_t)32 * 32 * 512];
__device__ uint4 g_axl[(size_t)32 * 32 * 512];
__device__ uint4 g_buh[(size_t)32 * 32 * 512];   // uint2 pairs viewed as uint4
__device__ uint4 g_bul[(size_t)32 * 32 * 512];
// GEMM2 bf16 packed operands (R7 layout)
__device__ uint4 g_dh[(size_t)cfg::Dd * cfg::Ff / 8];
__device__ uint4 g_dl[(size_t)cfg::Dd * cfg::Ff / 8];
__device__ uint4 g_ratep[(size_t)cfg::M * cfg::Ff / 8];
__device__ float g_colsum[cfg::Ff];

// ------------------------------------------------------------------ helpers
__device__ __forceinline__ uint32_t pack_h2(float a, float b) {
    __half2 p = __floats2half2_rn(a, b);       // .x = a (low half)
    return *(uint32_t*)&p;
}
__device__ __forceinline__ uint32_t pack_bf2(float a, float b) {
    __nv_bfloat162 p = __floats2bfloat162_rn(a, b);
    return *(uint32_t*)&p;
}
__device__ __forceinline__ void mma_f16(float c[4], const uint4& a, const uint2& b) {
    asm volatile(
        "mma.sync.aligned.m16n8k16.row.col.f32.f16.f16.f32 "
        "{%0,%1,%2,%3}, {%4,%5,%6,%7}, {%8,%9}, {%0,%1,%2,%3};"
        : "+f"(c[0]), "+f"(c[1]), "+f"(c[2]), "+f"(c[3])
        : "r"(a.x), "r"(a.y), "r"(a.z), "r"(a.w), "r"(b.x), "r"(b.y));
}
__device__ __forceinline__ void mma_bf16(float c[4], const uint4& a, const uint2& b) {
    asm volatile(
        "mma.sync.aligned.m16n8k16.row.col.f32.bf16.bf16.f32 "
        "{%0,%1,%2,%3}, {%4,%5,%6,%7}, {%8,%9}, {%0,%1,%2,%3};"
        : "+f"(c[0]), "+f"(c[1]), "+f"(c[2]), "+f"(c[3])
        : "r"(a.x), "r"(a.y), "r"(a.z), "r"(a.w), "r"(b.x), "r"(b.y));
}
__device__ __forceinline__ void cp16(uint32_t sdst, const void* gsrc) {
    asm volatile("cp.async.cg.shared.global [%0], [%1], 16;" :: "r"(sdst), "l"(gsrc));
}
#define CP_COMMIT() asm volatile("cp.async.commit_group;" ::: "memory")

__device__ __forceinline__ float spike_rate_of(float h, float be, int T, float invT) {
    float v = 0.0f; int cnt = 0;
    for (int t = 0; t < T; t++) {
        v = be * v + h;
        if (v > 1.0f) { cnt++; v -= 1.0f; }
    }
    return (float)cnt * invT;
}

// -------------------------------------------------------------- pack kernels
// x [M, K=1024] -> fp16 hi/lo A-fragments (no scale; x_lo flush negligible)
__global__ void pack_a_f16(const float* __restrict__ src,
                           uint4* __restrict__ hi, uint4* __restrict__ lo)
{
    constexpr int K = 1024, KB = K / 16;                 // 64 k-blocks
    const int wg   = (blockIdx.x * 256 + threadIdx.x) >> 5;
    const int lane = threadIdx.x & 31;
    const int rbg = wg / KB, kbg = wg % KB;              // rbg 0..255
    const int gq = lane >> 2, tq = lane & 3;
    const float* s = src + (size_t)(rbg * 16) * K + kbg * 16;
    float v[8];
    v[0] = s[(size_t)gq * K + 2 * tq];       v[1] = s[(size_t)gq * K + 2 * tq + 1];
    v[2] = s[(size_t)(gq + 8) * K + 2 * tq]; v[3] = s[(size_t)(gq + 8) * K + 2 * tq + 1];
    v[4] = s[(size_t)gq * K + 2 * tq + 8];   v[5] = s[(size_t)gq * K + 2 * tq + 9];
    v[6] = s[(size_t)(gq + 8) * K + 2 * tq + 8]; v[7] = s[(size_t)(gq + 8) * K + 2 * tq + 9];
    float h[8], l[8];
    #pragma unroll
    for (int i = 0; i < 8; i++) {
        h[i] = __half2float(__float2half_rn(v[i]));
        l[i] = v[i] - h[i];
    }
    const int mtile = rbg >> 3, rb = rbg & 7, kc = kbg >> 1, kb = kbg & 1;
    const size_t idx = (((size_t)kc * 32 + mtile) * 16 + rb * 2 + kb) * 32 + lane;
    hi[idx] = make_uint4(pack_h2(h[0], h[1]), pack_h2(h[2], h[3]),
                         pack_h2(h[4], h[5]), pack_h2(h[6], h[7]));
    lo[idx] = make_uint4(pack_h2(l[0], l[1]), pack_h2(l[2], l[3]),
                         pack_h2(l[4], l[5]), pack_h2(l[6], l[7]));
}

// w_up [N=4096, K=1024] scaled by 2^8 -> fp16 hi/lo B-fragments
__global__ void pack_b_f16(const float* __restrict__ src,
                           uint2* __restrict__ hi, uint2* __restrict__ lo)
{
    constexpr int K = 1024, KB = K / 16;
    const int wg   = (blockIdx.x * 256 + threadIdx.x) >> 5;
    const int lane = threadIdx.x & 31;
    const int nbg = wg / KB, kbg = wg % KB;              // nbg 0..511
    const int gq = lane >> 2, tq = lane & 3;
    const float* s = src + (size_t)(nbg * 8 + gq) * K + kbg * 16;
    const float v0 = s[2 * tq] * 256.0f,     v1 = s[2 * tq + 1] * 256.0f;
    const float v2 = s[2 * tq + 8] * 256.0f, v3 = s[2 * tq + 9] * 256.0f;
    const float h0 = __half2float(__float2half_rn(v0));
    const float h1 = __half2float(__float2half_rn(v1));
    const float h2 = __half2float(__float2half_rn(v2));
    const float h3 = __half2float(__float2half_rn(v3));
    const int ntile = nbg >> 4, nb = nbg & 15, kc = kbg >> 1, kb = kbg & 1;
    const size_t idx = ((((size_t)kc * 32 + ntile) * 16 + nb) * 2 + kb) * 32 + lane;
    hi[idx] = make_uint2(pack_h2(h0, h1), pack_h2(h2, h3));
    lo[idx] = make_uint2(pack_h2(v0 - h0, v1 - h1), pack_h2(v2 - h2, v3 - h3));
}

// w_down [N=1024, K=4096] -> bf16 hi/lo (R7 layout, unchanged)
__global__ void pack_b_bf16(const float* __restrict__ src,
                            uint2* __restrict__ hi, uint2* __restrict__ lo)
{
    constexpr int K = 4096, KB16 = K / 16;
    const int wg   = (blockIdx.x * 256 + threadIdx.x) >> 5;
    const int lane = threadIdx.x & 31;
    const int nbg = wg / KB16, kbg = wg % KB16;
    const int gq = lane >> 2, tq = lane & 3;
    const float* s = src + (size_t)(nbg * 8 + gq) * K + kbg * 16;
    const float v0 = s[2 * tq], v1 = s[2 * tq + 1];
    const float v2 = s[2 * tq + 8], v3 = s[2 * tq + 9];
    const float h0 = __bfloat162float(__float2bfloat16_rn(v0));
    const float h1 = __bfloat162float(__float2bfloat16_rn(v1));
    const float h2 = __bfloat162float(__float2bfloat16_rn(v2));
    const float h3 = __bfloat162float(__float2bfloat16_rn(v3));
    const int ntile = nbg >> 4, nb = nbg & 15, kc = kbg >> 2, kb = kbg & 3;
    const size_t idx = ((((size_t)kc * 8 + ntile) * 16 + nb) * 4 + kb) * 32 + lane;
    hi[idx] = make_uint2(pack_bf2(h0, h1), pack_bf2(h2, h3));
    lo[idx] = make_uint2(pack_bf2(v0 - h0, v1 - h1), pack_bf2(v2 - h2, v3 - h3));
}

__global__ void zero_colsum() { g_colsum[blockIdx.x * 256 + threadIdx.x] = 0.0f; }
__global__ void finalize_rpu(float* __restrict__ rpu) {
    const int f = blockIdx.x * 256 + threadIdx.x;
    rpu[f] = g_colsum[f] * (1.0f / (float)cfg::M);   // exact
}

// --------------------------------------------------- GEMM1 (fp16, 3 passes)
// h_scaled = xh*uh + xh*ul + xl*uh (u pre-scaled by 2^8); h = h_scaled * 2^-8.
__global__ __launch_bounds__(256, 2)
void tc_gemm1(const float* __restrict__ beta, const int* __restrict__ Tptr)
{
    constexpr int TILE  = 8192;                  // bytes per operand tile (128x32 fp16)
    constexpr int STAGE = 4 * TILE;              // Ah, Al, Bh, Bl
    constexpr int NC    = cfg::Dd / 32;          // 32 chunks
    constexpr int STAGES = 3;
    extern __shared__ char smc[];

    const int tid = threadIdx.x, lane = tid & 31, wid = tid >> 5;
    const int gq = lane >> 2, tq = lane & 3;
    const int mtile = blockIdx.y, ntile = blockIdx.x;
    const int colBase = ntile * 128;
    const int rbb = (wid & 1) * 4, nbb = (wid >> 1) * 4;
    const int wm = (wid & 1) * 64, wn = (wid >> 1) * 32;
    const uint32_t sb = (uint32_t)__cvta_generic_to_shared(smc);
    float* sm = (float*)smc;

    const uint4* pAh = g_axh + (size_t)mtile * 512;
    const uint4* pAl = g_axl + (size_t)mtile * 512;
    const uint4* pBh = g_buh + (size_t)ntile * 512;
    const uint4* pBl = g_bul + (size_t)ntile * 512;
    constexpr size_t strideKC = (size_t)32 * 512;     // per-kc stride (uint4)

    auto stage_load = [&](int c, int st) {
        const uint32_t d = sb + (uint32_t)st * STAGE;
        const size_t o = (size_t)c * strideKC;
        #pragma unroll
        for (int q = 0; q < 2; q++) {
            const int idx = q * 256 + tid;
            cp16(d + idx * 16,            pAh + o + idx);
            cp16(d + TILE + idx * 16,     pAl + o + idx);
            cp16(d + 2 * TILE + idx * 16, pBh + o + idx);
            cp16(d + 3 * TILE + idx * 16, pBl + o + idx);
        }
    };

    float acc[4][4][4];
    #pragma unroll
    for (int mi = 0; mi < 4; mi++)
        #pragma unroll
        for (int ni = 0; ni < 4; ni++)
            #pragma unroll
            for (int q = 0; q < 4; q++) acc[mi][ni][q] = 0.0f;

    #pragma unroll
    for (int s = 0; s < STAGES; s++) { stage_load(s, s); CP_COMMIT(); }

    int st = 0;
    for (int c = 0; c < NC; c++) {
        asm volatile("cp.async.wait_group 2;" ::: "memory");
        __syncthreads();
        const uint4* ahs = (const uint4*)(smc + st * STAGE);
        const uint4* als = (const uint4*)(smc + st * STAGE + TILE);
        const uint2* bhs = (const uint2*)(smc + st * STAGE + 2 * TILE);
        const uint2* bls = (const uint2*)(smc + st * STAGE + 3 * TILE);

        #pragma unroll
        for (int ks = 0; ks < 2; ks++) {
            uint2 bh[4], bl[4];
            #pragma unroll
            for (int ni = 0; ni < 4; ni++) {
                bh[ni] = bhs[((nbb + ni) * 2 + ks) * 32 + lane];
                bl[ni] = bls[((nbb + ni) * 2 + ks) * 32 + lane];
            }
            #pragma unroll
            for (int mp = 0; mp < 2; mp++) {
                const int m0 = 2 * mp, m1 = 2 * mp + 1;
                const uint4 a0 = ahs[((rbb + m0) * 2 + ks) * 32 + lane];
                const uint4 a1 = ahs[((rbb + m1) * 2 + ks) * 32 + lane];
                #pragma unroll
                for (int ni = 0; ni < 4; ni++) mma_f16(acc[m0][ni], a0, bh[ni]);
                #pragma unroll
                for (int ni = 0; ni < 4; ni++) mma_f16(acc[m1][ni], a1, bh[ni]);
                #pragma unroll
                for (int ni = 0; ni < 4; ni++) mma_f16(acc[m0][ni], a0, bl[ni]);
                #pragma unroll
                for (int ni = 0; ni < 4; ni++) mma_f16(acc[m1][ni], a1, bl[ni]);
                const uint4 l0 = als[((rbb + m0) * 2 + ks) * 32 + lane];
                const uint4 l1 = als[((rbb + m1) * 2 + ks) * 32 + lane];
                #pragma unroll
                for (int ni = 0; ni < 4; ni++) mma_f16(acc[m0][ni], l0, bh[ni]);
                #pragma unroll
                for (int ni = 0; ni < 4; ni++) mma_f16(acc[m1][ni], l1, bh[ni]);
            }
        }
        __syncthreads();
        if (c + STAGES < NC) stage_load(c + STAGES, st);
        CP_COMMIT();
        st = (st + 1 == STAGES) ? 0 : st + 1;
    }

    // epilogue: unscale (exact 2^-8), spike -> smem tile, colsum + bf16 ratep
    constexpr float SC = 1.0f / 256.0f;
    const int   T    = *Tptr;
    const float invT = 1.0f / (float)T;
    __syncthreads();
    #pragma unroll
    for (int ni = 0; ni < 4; ni++) {
        const int cl = wn + ni * 8 + 2 * tq;
        const float be0 = beta[colBase + cl];
        const float be1 = beta[colBase + cl + 1];
        #pragma unroll
        for (int mi = 0; mi < 4; mi++) {
            const int r0 = wm + mi * 16 + gq;
            sm[r0 * 132 + cl]           = spike_rate_of(acc[mi][ni][0] * SC, be0, T, invT);
            sm[r0 * 132 + cl + 1]       = spike_rate_of(acc[mi][ni][1] * SC, be1, T, invT);
            sm[(r0 + 8) * 132 + cl]     = spike_rate_of(acc[mi][ni][2] * SC, be0, T, invT);
            sm[(r0 + 8) * 132 + cl + 1] = spike_rate_of(acc[mi][ni][3] * SC, be1, T, invT);
        }
    }
    __syncthreads();
    if (tid < 128) {
        float s = 0.0f;
        #pragma unroll 8
        for (int r = 0; r < 128; r++) s += sm[r * 132 + tid];
        atomicAdd(&g_colsum[colBase + tid], s);   // exact: multiples of 1/8
    }
    // write rate (exact bf16) in GEMM2-A packed layout (R7):
    #pragma unroll
    for (int i = 0; i < 8; i++) {
        const int idx = i * 256 + tid;
        const int l2  = idx & 31;
        const int t2  = idx >> 5;
        const int kcj = t2 >> 5;
        const int pos = t2 & 31;
        const int g2 = l2 >> 2, q2 = l2 & 3;
        const int ml = (pos >> 2) * 16;
        const int fl = kcj * 64 + (pos & 3) * 16;
        const int ra = ml + g2, rb2 = ml + g2 + 8;
        const int c0 = fl + 2 * q2, c8 = fl + 2 * q2 + 8;
        uint4 v;
        v.x = pack_bf2(sm[ra * 132 + c0],  sm[ra * 132 + c0 + 1]);
        v.y = pack_bf2(sm[rb2 * 132 + c0], sm[rb2 * 132 + c0 + 1]);
        v.z = pack_bf2(sm[ra * 132 + c8],  sm[ra * 132 + c8 + 1]);
        v.w = pack_bf2(sm[rb2 * 132 + c8], sm[rb2 * 132 + c8 + 1]);
        g_ratep[((size_t)(colBase / 64 + kcj) * 32 + mtile) * 1024 + pos * 32 + l2] = v;
    }
}

// --------------------------------------------- GEMM2 (bf16, 2 passes; = R7)
__global__ __launch_bounds__(256, 2)
void tc_gemm2(const uint4* __restrict__ A, const uint4* __restrict__ Bh,
              const uint4* __restrict__ Bl, float* __restrict__ C)
{
    constexpr int TILE = 16384;
    constexpr int STAGE = 3 * TILE;
    constexpr int NC = cfg::Ff / 64;
    extern __shared__ char smc[];

    const int tid = threadIdx.x, lane = tid & 31, wid = tid >> 5;
    const int gq = lane >> 2, tq = lane & 3;
    const int mtile = blockIdx.y, ntile = blockIdx.x;
    const int rowBase = mtile * 128, colBase = ntile * 128;
    const int rbb = (wid & 1) * 4, nbb = (wid >> 1) * 4;
    const int wm = (wid & 1) * 64, wn = (wid >> 1) * 32;
    const uint32_t sb = (uint32_t)__cvta_generic_to_shared(smc);

    const uint4* pA  = A  + (size_t)mtile * 1024;
    const uint4* pBh = Bh + (size_t)ntile * 1024;
    const uint4* pBl = Bl + (size_t)ntile * 1024;
    constexpr size_t strideA = (size_t)32 * 1024;
    constexpr size_t strideB = (size_t)8 * 1024;

    auto stage_load = [&](int c, int st) {
        const uint32_t d = sb + (uint32_t)st * STAGE;
        const uint4* a  = pA  + (size_t)c * strideA;
        const uint4* b0 = pBh + (size_t)c * strideB;
        const uint4* b1 = pBl + (size_t)c * strideB;
        #pragma unroll
        for (int q = 0; q < 4; q++) {
            const int idx = q * 256 + tid;
            cp16(d + idx * 16, a + idx);
            cp16(d + TILE + idx * 16, b0 + idx);
            cp16(d + 2 * TILE + idx * 16, b1 + idx);
        }
    };

    float acc[4][4][4];
    #pragma unroll
    for (int mi = 0; mi < 4; mi++)
        #pragma unroll
        for (int ni = 0; ni < 4; ni++)
            #pragma unroll
            for (int q = 0; q < 4; q++) acc[mi][ni][q] = 0.0f;

    stage_load(0, 0); CP_COMMIT();
    stage_load(1, 1); CP_COMMIT();

    int st = 0;
    for (int c = 0; c < NC; c++) {
        asm volatile("cp.async.wait_group 1;" ::: "memory");
        __syncthreads();
        const uint4* ahs = (const uint4*)(smc + st * STAGE);
        const uint2* bhs = (const uint2*)(smc + st * STAGE + TILE);
        const uint2* bls = (const uint2*)(smc + st * STAGE + 2 * TILE);

        #pragma unroll
        for (int ks = 0; ks < 4; ks++) {
            uint2 bh[4], bl[4];
            #pragma unroll
            for (int ni = 0; ni < 4; ni++) {
                bh[ni] = bhs[((nbb + ni) * 4 + ks) * 32 + lane];
                bl[ni] = bls[((nbb + ni) * 4 + ks) * 32 + lane];
            }
            #pragma unroll
            for (int mp = 0; mp < 2; mp++) {
                const int m0 = 2 * mp, m1 = 2 * mp + 1;
                const uint4 a0 = ahs[((rbb + m0) * 4 + ks) * 32 + lane];
                const uint4 a1 = ahs[((rbb + m1) * 4 + ks) * 32 + lane];
                #pragma unroll
                for (int ni = 0; ni < 4; ni++) mma_bf16(acc[m0][ni], a0, bh[ni]);
                #pragma unroll
                for (int ni = 0; ni < 4; ni++) mma_bf16(acc[m1][ni], a1, bh[ni]);
                #pragma unroll
                for (int ni = 0; ni < 4; ni++) mma_bf16(acc[m0][ni], a0, bl[ni]);
                #pragma unroll
                for (int ni = 0; ni < 4; ni++) mma_bf16(acc[m1][ni], a1, bl[ni]);
            }
        }
        __syncthreads();
        if (c + 2 < NC) stage_load(c + 2, st);
        CP_COMMIT();
        st ^= 1;
    }

    #pragma unroll
    for (int ni = 0; ni < 4; ni++) {
        const int cglob = colBase + wn + ni * 8 + 2 * tq;
        #pragma unroll
        for (int mi = 0; mi < 4; mi++) {
            const int r0 = rowBase + wm + mi * 16 + gq;
            *(float2*)(C + (size_t)r0 * cfg::Dd + cglob) =
                make_float2(acc[mi][ni][0], acc[mi][ni][1]);
            *(float2*)(C + (size_t)(r0 + 8) * cfg::Dd + cglob) =
                make_float2(acc[mi][ni][2], acc[mi][ni][3]);
        }
    }
}

// -------------------------------------------------------------------- launch
extern "C" void kernel_launch(void* const* d_in, const int* in_sizes, int n_in,
                              void* d_out, int out_size)
{
    const float* x      = (const float*)d_in[0];
    const float* w_up   = (const float*)d_in[1];
    const float* w_down = (const float*)d_in[2];
    const float* beta   = (const float*)d_in[3];
    const int*   Tptr   = (const int*)d_in[4];

    float* out = (float*)d_out;
    float* rpu = out + (size_t)cfg::M * cfg::Dd;

    uint4 *axh, *axl, *buh, *bul, *dh, *dl, *ratep;
    cudaGetSymbolAddress((void**)&axh, g_axh);
    cudaGetSymbolAddress((void**)&axl, g_axl);
    cudaGetSymbolAddress((void**)&buh, g_buh);
    cudaGetSymbolAddress((void**)&bul, g_bul);
    cudaGetSymbolAddress((void**)&dh, g_dh);
    cudaGetSymbolAddress((void**)&dl, g_dl);
    cudaGetSymbolAddress((void**)&ratep, g_ratep);

    zero_colsum<<<cfg::Ff / 256, 256>>>();
    pack_a_f16<<<2048, 256>>>(x, axh, axl);                      // 16384 warps
    pack_b_f16<<<4096, 256>>>(w_up, (uint2*)buh, (uint2*)bul);   // 32768 warps
    pack_b_bf16<<<4096, 256>>>(w_down, (uint2*)dh, (uint2*)dl);  // 32768 warps

    constexpr int SMEM1 = 3 * 4 * 8192;    // 98304 B
    constexpr int SMEM2 = 2 * 3 * 16384;   // 98304 B
    cudaFuncSetAttribute(tc_gemm1, cudaFuncAttributeMaxDynamicSharedMemorySize, SMEM1);
    cudaFuncSetAttribute(tc_gemm2, cudaFuncAttributeMaxDynamicSharedMemorySize, SMEM2);

    tc_gemm1<<<dim3(cfg::Ff / 128, cfg::M / 128), 256, SMEM1>>>(beta, Tptr);

    finalize_rpu<<<cfg::Ff / 256, 256>>>(rpu);

    tc_gemm2<<<dim3(cfg::Dd / 128, cfg::M / 128), 256, SMEM2>>>(ratep, dh, dl, out);
}

// round 9
// speedup vs baseline: 3.2492x; 1.1876x over previous
#include <cuda_runtime.h>
#include <cuda_fp16.h>
#include <cstdint>

// SpikingMLP:
//   GEMM1 (fp16 m16n8k16 3-pass, w_up scaled by 2^8): rate = spike_rate(x @ w_up^T)
//   GEMM2 (fp16 m16n8k16 SINGLE pass, w_down scaled by 2^4): out = rate @ w_down^T / 2^4
//   rate is exact in fp16 (multiples of 1/8); scalings are exact powers of 2.
//   rate_per_unit via exact atomic column sums in GEMM1 epilogue.

namespace cfg {
constexpr int M  = 4096;
constexpr int Dd = 1024;
constexpr int Ff = 4096;
}

// GEMM1 fp16 packed operands: A [kc(32)][mtile(32)][rb(8)][kb(2)][lane(32)] uint4
//                             B [kc(32)][ntile(32)][nb(16)][kb(2)][lane(32)] uint2
__device__ uint4 g_axh[(size_t)32 * 32 * 512];
__device__ uint4 g_axl[(size_t)32 * 32 * 512];
__device__ uint4 g_buh[(size_t)32 * 32 * 512];
__device__ uint4 g_bul[(size_t)32 * 32 * 512];
// GEMM2 fp16 operands
__device__ uint4 g_dw[(size_t)cfg::Dd * cfg::Ff / 8];    // w_down * 2^4, fragment-packed
__device__ uint4 g_ratep[(size_t)cfg::M * cfg::Ff / 8];  // rate as fp16, GEMM2-A packed
__device__ float g_colsum[cfg::Ff];

// ------------------------------------------------------------------ helpers
__device__ __forceinline__ uint32_t pack_h2(float a, float b) {
    __half2 p = __floats2half2_rn(a, b);       // .x = a (low half)
    return *(uint32_t*)&p;
}
__device__ __forceinline__ void mma_f16(float c[4], const uint4& a, const uint2& b) {
    asm volatile(
        "mma.sync.aligned.m16n8k16.row.col.f32.f16.f16.f32 "
        "{%0,%1,%2,%3}, {%4,%5,%6,%7}, {%8,%9}, {%0,%1,%2,%3};"
        : "+f"(c[0]), "+f"(c[1]), "+f"(c[2]), "+f"(c[3])
        : "r"(a.x), "r"(a.y), "r"(a.z), "r"(a.w), "r"(b.x), "r"(b.y));
}
__device__ __forceinline__ void cp16(uint32_t sdst, const void* gsrc) {
    asm volatile("cp.async.cg.shared.global [%0], [%1], 16;" :: "r"(sdst), "l"(gsrc));
}
#define CP_COMMIT() asm volatile("cp.async.commit_group;" ::: "memory")

__device__ __forceinline__ float spike_rate_of(float h, float be, int T, float invT) {
    float v = 0.0f; int cnt = 0;
    for (int t = 0; t < T; t++) {
        v = be * v + h;
        if (v > 1.0f) { cnt++; v -= 1.0f; }
    }
    return (float)cnt * invT;
}

// -------------------------------------------------------------- pack kernels
// x [M, K=1024] -> fp16 hi/lo A-fragments
__global__ void pack_a_f16(const float* __restrict__ src,
                           uint4* __restrict__ hi, uint4* __restrict__ lo)
{
    constexpr int K = 1024, KB = K / 16;
    const int wg   = (blockIdx.x * 256 + threadIdx.x) >> 5;
    const int lane = threadIdx.x & 31;
    const int rbg = wg / KB, kbg = wg % KB;
    const int gq = lane >> 2, tq = lane & 3;
    const float* s = src + (size_t)(rbg * 16) * K + kbg * 16;
    float v[8];
    v[0] = s[(size_t)gq * K + 2 * tq];       v[1] = s[(size_t)gq * K + 2 * tq + 1];
    v[2] = s[(size_t)(gq + 8) * K + 2 * tq]; v[3] = s[(size_t)(gq + 8) * K + 2 * tq + 1];
    v[4] = s[(size_t)gq * K + 2 * tq + 8];   v[5] = s[(size_t)gq * K + 2 * tq + 9];
    v[6] = s[(size_t)(gq + 8) * K + 2 * tq + 8]; v[7] = s[(size_t)(gq + 8) * K + 2 * tq + 9];
    float h[8], l[8];
    #pragma unroll
    for (int i = 0; i < 8; i++) {
        h[i] = __half2float(__float2half_rn(v[i]));
        l[i] = v[i] - h[i];
    }
    const int mtile = rbg >> 3, rb = rbg & 7, kc = kbg >> 1, kb = kbg & 1;
    const size_t idx = (((size_t)kc * 32 + mtile) * 16 + rb * 2 + kb) * 32 + lane;
    hi[idx] = make_uint4(pack_h2(h[0], h[1]), pack_h2(h[2], h[3]),
                         pack_h2(h[4], h[5]), pack_h2(h[6], h[7]));
    lo[idx] = make_uint4(pack_h2(l[0], l[1]), pack_h2(l[2], l[3]),
                         pack_h2(l[4], l[5]), pack_h2(l[6], l[7]));
}

// w_up [N=4096, K=1024] scaled by 2^8 -> fp16 hi/lo B-fragments
__global__ void pack_b_f16(const float* __restrict__ src,
                           uint2* __restrict__ hi, uint2* __restrict__ lo)
{
    constexpr int K = 1024, KB = K / 16;
    const int wg   = (blockIdx.x * 256 + threadIdx.x) >> 5;
    const int lane = threadIdx.x & 31;
    const int nbg = wg / KB, kbg = wg % KB;
    const int gq = lane >> 2, tq = lane & 3;
    const float* s = src + (size_t)(nbg * 8 + gq) * K + kbg * 16;
    const float v0 = s[2 * tq] * 256.0f,     v1 = s[2 * tq + 1] * 256.0f;
    const float v2 = s[2 * tq + 8] * 256.0f, v3 = s[2 * tq + 9] * 256.0f;
    const float h0 = __half2float(__float2half_rn(v0));
    const float h1 = __half2float(__float2half_rn(v1));
    const float h2 = __half2float(__float2half_rn(v2));
    const float h3 = __half2float(__float2half_rn(v3));
    const int ntile = nbg >> 4, nb = nbg & 15, kc = kbg >> 1, kb = kbg & 1;
    const size_t idx = ((((size_t)kc * 32 + ntile) * 16 + nb) * 2 + kb) * 32 + lane;
    hi[idx] = make_uint2(pack_h2(h0, h1), pack_h2(h2, h3));
    lo[idx] = make_uint2(pack_h2(v0 - h0, v1 - h1), pack_h2(v2 - h2, v3 - h3));
}

// w_down [N=1024, K=4096] scaled by 2^4 -> single fp16, GEMM2-B layout
// [kc(64)][ntile(8)][nb(16)][kb(4)][lane(32)][uint2 = 4 fp16]
__global__ void pack_w_down_f16(const float* __restrict__ src,
                                uint2* __restrict__ dst)
{
    constexpr int K = 4096, KB16 = K / 16;
    const int wg   = (blockIdx.x * 256 + threadIdx.x) >> 5;
    const int lane = threadIdx.x & 31;
    const int nbg = wg / KB16, kbg = wg % KB16;
    const int gq = lane >> 2, tq = lane & 3;
    const float* s = src + (size_t)(nbg * 8 + gq) * K + kbg * 16;
    const float v0 = s[2 * tq] * 16.0f,     v1 = s[2 * tq + 1] * 16.0f;
    const float v2 = s[2 * tq + 8] * 16.0f, v3 = s[2 * tq + 9] * 16.0f;
    const int ntile = nbg >> 4, nb = nbg & 15, kc = kbg >> 2, kb = kbg & 3;
    const size_t idx = ((((size_t)kc * 8 + ntile) * 16 + nb) * 4 + kb) * 32 + lane;
    dst[idx] = make_uint2(pack_h2(v0, v1), pack_h2(v2, v3));
}

__global__ void zero_colsum() { g_colsum[blockIdx.x * 256 + threadIdx.x] = 0.0f; }
__global__ void finalize_rpu(float* __restrict__ rpu) {
    const int f = blockIdx.x * 256 + threadIdx.x;
    rpu[f] = g_colsum[f] * (1.0f / (float)cfg::M);   // exact
}

// --------------------------------------------------- GEMM1 (fp16, 3 passes)
__global__ __launch_bounds__(256, 2)
void tc_gemm1(const float* __restrict__ beta, const int* __restrict__ Tptr)
{
    constexpr int TILE  = 8192;
    constexpr int STAGE = 4 * TILE;
    constexpr int NC    = cfg::Dd / 32;
    constexpr int STAGES = 3;
    extern __shared__ char smc[];

    const int tid = threadIdx.x, lane = tid & 31, wid = tid >> 5;
    const int gq = lane >> 2, tq = lane & 3;
    const int mtile = blockIdx.y, ntile = blockIdx.x;
    const int colBase = ntile * 128;
    const int rbb = (wid & 1) * 4, nbb = (wid >> 1) * 4;
    const int wm = (wid & 1) * 64, wn = (wid >> 1) * 32;
    const uint32_t sb = (uint32_t)__cvta_generic_to_shared(smc);
    float* sm = (float*)smc;

    const uint4* pAh = g_axh + (size_t)mtile * 512;
    const uint4* pAl = g_axl + (size_t)mtile * 512;
    const uint4* pBh = g_buh + (size_t)ntile * 512;
    const uint4* pBl = g_bul + (size_t)ntile * 512;
    constexpr size_t strideKC = (size_t)32 * 512;

    auto stage_load = [&](int c, int st) {
        const uint32_t d = sb + (uint32_t)st * STAGE;
        const size_t o = (size_t)c * strideKC;
        #pragma unroll
        for (int q = 0; q < 2; q++) {
            const int idx = q * 256 + tid;
            cp16(d + idx * 16,            pAh + o + idx);
            cp16(d + TILE + idx * 16,     pAl + o + idx);
            cp16(d + 2 * TILE + idx * 16, pBh + o + idx);
            cp16(d + 3 * TILE + idx * 16, pBl + o + idx);
        }
    };

    float acc[4][4][4];
    #pragma unroll
    for (int mi = 0; mi < 4; mi++)
        #pragma unroll
        for (int ni = 0; ni < 4; ni++)
            #pragma unroll
            for (int q = 0; q < 4; q++) acc[mi][ni][q] = 0.0f;

    #pragma unroll
    for (int s = 0; s < STAGES; s++) { stage_load(s, s); CP_COMMIT(); }

    int st = 0;
    for (int c = 0; c < NC; c++) {
        asm volatile("cp.async.wait_group 2;" ::: "memory");
        __syncthreads();
        const uint4* ahs = (const uint4*)(smc + st * STAGE);
        const uint4* als = (const uint4*)(smc + st * STAGE + TILE);
        const uint2* bhs = (const uint2*)(smc + st * STAGE + 2 * TILE);
        const uint2* bls = (const uint2*)(smc + st * STAGE + 3 * TILE);

        #pragma unroll
        for (int ks = 0; ks < 2; ks++) {
            uint2 bh[4], bl[4];
            #pragma unroll
            for (int ni = 0; ni < 4; ni++) {
                bh[ni] = bhs[((nbb + ni) * 2 + ks) * 32 + lane];
                bl[ni] = bls[((nbb + ni) * 2 + ks) * 32 + lane];
            }
            #pragma unroll
            for (int mp = 0; mp < 2; mp++) {
                const int m0 = 2 * mp, m1 = 2 * mp + 1;
                const uint4 a0 = ahs[((rbb + m0) * 2 + ks) * 32 + lane];
                const uint4 a1 = ahs[((rbb + m1) * 2 + ks) * 32 + lane];
                #pragma unroll
                for (int ni = 0; ni < 4; ni++) mma_f16(acc[m0][ni], a0, bh[ni]);
                #pragma unroll
                for (int ni = 0; ni < 4; ni++) mma_f16(acc[m1][ni], a1, bh[ni]);
                #pragma unroll
                for (int ni = 0; ni < 4; ni++) mma_f16(acc[m0][ni], a0, bl[ni]);
                #pragma unroll
                for (int ni = 0; ni < 4; ni++) mma_f16(acc[m1][ni], a1, bl[ni]);
                const uint4 l0 = als[((rbb + m0) * 2 + ks) * 32 + lane];
                const uint4 l1 = als[((rbb + m1) * 2 + ks) * 32 + lane];
                #pragma unroll
                for (int ni = 0; ni < 4; ni++) mma_f16(acc[m0][ni], l0, bh[ni]);
                #pragma unroll
                for (int ni = 0; ni < 4; ni++) mma_f16(acc[m1][ni], l1, bh[ni]);
            }
        }
        __syncthreads();
        if (c + STAGES < NC) stage_load(c + STAGES, st);
        CP_COMMIT();
        st = (st + 1 == STAGES) ? 0 : st + 1;
    }

    // epilogue: unscale 2^-8, spike -> smem tile, colsum + fp16 ratep
    constexpr float SC = 1.0f / 256.0f;
    const int   T    = *Tptr;
    const float invT = 1.0f / (float)T;
    __syncthreads();
    #pragma unroll
    for (int ni = 0; ni < 4; ni++) {
        const int cl = wn + ni * 8 + 2 * tq;
        const float be0 = beta[colBase + cl];
        const float be1 = beta[colBase + cl + 1];
        #pragma unroll
        for (int mi = 0; mi < 4; mi++) {
            const int r0 = wm + mi * 16 + gq;
            sm[r0 * 132 + cl]           = spike_rate_of(acc[mi][ni][0] * SC, be0, T, invT);
            sm[r0 * 132 + cl + 1]       = spike_rate_of(acc[mi][ni][1] * SC, be1, T, invT);
            sm[(r0 + 8) * 132 + cl]     = spike_rate_of(acc[mi][ni][2] * SC, be0, T, invT);
            sm[(r0 + 8) * 132 + cl + 1] = spike_rate_of(acc[mi][ni][3] * SC, be1, T, invT);
        }
    }
    __syncthreads();
    if (tid < 128) {
        float s = 0.0f;
        #pragma unroll 8
        for (int r = 0; r < 128; r++) s += sm[r * 132 + tid];
        atomicAdd(&g_colsum[colBase + tid], s);   // exact: multiples of 1/8
    }
    // write rate (exact fp16) in GEMM2-A packed layout:
    // [kc2(F/64)][mtile(32)][rb(8)][kb2(4)][lane(32)][uint4 = 8 fp16]
    #pragma unroll
    for (int i = 0; i < 8; i++) {
        const int idx = i * 256 + tid;
        const int l2  = idx & 31;
        const int t2  = idx >> 5;
        const int kcj = t2 >> 5;
        const int pos = t2 & 31;
        const int g2 = l2 >> 2, q2 = l2 & 3;
        const int ml = (pos >> 2) * 16;
        const int fl = kcj * 64 + (pos & 3) * 16;
        const int ra = ml + g2, rb2 = ml + g2 + 8;
        const int c0 = fl + 2 * q2, c8 = fl + 2 * q2 + 8;
        uint4 v;
        v.x = pack_h2(sm[ra * 132 + c0],  sm[ra * 132 + c0 + 1]);
        v.y = pack_h2(sm[rb2 * 132 + c0], sm[rb2 * 132 + c0 + 1]);
        v.z = pack_h2(sm[ra * 132 + c8],  sm[ra * 132 + c8 + 1]);
        v.w = pack_h2(sm[rb2 * 132 + c8], sm[rb2 * 132 + c8 + 1]);
        g_ratep[((size_t)(colBase / 64 + kcj) * 32 + mtile) * 1024 + pos * 32 + l2] = v;
    }
}

// --------------------------------------------- GEMM2 (fp16, SINGLE pass)
// out[M, Dd] = (rate @ (w_down*16)^T) * 2^-4
__global__ __launch_bounds__(256, 2)
void tc_gemm2(const uint4* __restrict__ A, const uint4* __restrict__ B,
              float* __restrict__ C)
{
    constexpr int TILE = 16384;                  // bytes: 128x64 fp16
    constexpr int STAGE = 2 * TILE;              // A + B
    constexpr int NC = cfg::Ff / 64;             // 64
    constexpr int STAGES = 3;
    extern __shared__ char smc[];

    const int tid = threadIdx.x, lane = tid & 31, wid = tid >> 5;
    const int gq = lane >> 2, tq = lane & 3;
    const int mtile = blockIdx.y, ntile = blockIdx.x;
    const int rowBase = mtile * 128, colBase = ntile * 128;
    const int rbb = (wid & 1) * 4, nbb = (wid >> 1) * 4;
    const int wm = (wid & 1) * 64, wn = (wid >> 1) * 32;
    const uint32_t sb = (uint32_t)__cvta_generic_to_shared(smc);

    const uint4* pA = A + (size_t)mtile * 1024;
    const uint4* pB = B + (size_t)ntile * 1024;
    constexpr size_t strideA = (size_t)32 * 1024;
    constexpr size_t strideB = (size_t)8 * 1024;

    auto stage_load = [&](int c, int st) {
        const uint32_t d = sb + (uint32_t)st * STAGE;
        const uint4* a = pA + (size_t)c * strideA;
        const uint4* b = pB + (size_t)c * strideB;
        #pragma unroll
        for (int q = 0; q < 4; q++) {
            const int idx = q * 256 + tid;
            cp16(d + idx * 16, a + idx);
            cp16(d + TILE + idx * 16, b + idx);
        }
    };

    float acc[4][4][4];
    #pragma unroll
    for (int mi = 0; mi < 4; mi++)
        #pragma unroll
        for (int ni = 0; ni < 4; ni++)
            #pragma unroll
            for (int q = 0; q < 4; q++) acc[mi][ni][q] = 0.0f;

    #pragma unroll
    for (int s = 0; s < STAGES; s++) { stage_load(s, s); CP_COMMIT(); }

    int st = 0;
    for (int c = 0; c < NC; c++) {
        asm volatile("cp.async.wait_group 2;" ::: "memory");
        __syncthreads();
        const uint4* ahs = (const uint4*)(smc + st * STAGE);
        const uint2* bhs = (const uint2*)(smc + st * STAGE + TILE);

        #pragma unroll
        for (int ks = 0; ks < 4; ks++) {
            uint2 bh[4];
            #pragma unroll
            for (int ni = 0; ni < 4; ni++)
                bh[ni] = bhs[((nbb + ni) * 4 + ks) * 32 + lane];
            #pragma unroll
            for (int mp = 0; mp < 2; mp++) {
                const int m0 = 2 * mp, m1 = 2 * mp + 1;
                const uint4 a0 = ahs[((rbb + m0) * 4 + ks) * 32 + lane];
                const uint4 a1 = ahs[((rbb + m1) * 4 + ks) * 32 + lane];
                #pragma unroll
                for (int ni = 0; ni < 4; ni++) mma_f16(acc[m0][ni], a0, bh[ni]);
                #pragma unroll
                for (int ni = 0; ni < 4; ni++) mma_f16(acc[m1][ni], a1, bh[ni]);
            }
        }
        __syncthreads();
        if (c + STAGES < NC) stage_load(c + STAGES, st);
        CP_COMMIT();
        st = (st + 1 == STAGES) ? 0 : st + 1;
    }

    constexpr float SC = 1.0f / 16.0f;           // exact unscale of w_down*16
    #pragma unroll
    for (int ni = 0; ni < 4; ni++) {
        const int cglob = colBase + wn + ni * 8 + 2 * tq;
        #pragma unroll
        for (int mi = 0; mi < 4; mi++) {
            const int r0 = rowBase + wm + mi * 16 + gq;
            *(float2*)(C + (size_t)r0 * cfg::Dd + cglob) =
                make_float2(acc[mi][ni][0] * SC, acc[mi][ni][1] * SC);
            *(float2*)(C + (size_t)(r0 + 8) * cfg::Dd + cglob) =
                make_float2(acc[mi][ni][2] * SC, acc[mi][ni][3] * SC);
        }
    }
}

// -------------------------------------------------------------------- launch
extern "C" void kernel_launch(void* const* d_in, const int* in_sizes, int n_in,
                              void* d_out, int out_size)
{
    const float* x      = (const float*)d_in[0];
    const float* w_up   = (const float*)d_in[1];
    const float* w_down = (const float*)d_in[2];
    const float* beta   = (const float*)d_in[3];
    const int*   Tptr   = (const int*)d_in[4];

    float* out = (float*)d_out;
    float* rpu = out + (size_t)cfg::M * cfg::Dd;

    uint4 *axh, *axl, *buh, *bul, *dw, *ratep;
    cudaGetSymbolAddress((void**)&axh, g_axh);
    cudaGetSymbolAddress((void**)&axl, g_axl);
    cudaGetSymbolAddress((void**)&buh, g_buh);
    cudaGetSymbolAddress((void**)&bul, g_bul);
    cudaGetSymbolAddress((void**)&dw, g_dw);
    cudaGetSymbolAddress((void**)&ratep, g_ratep);

    zero_colsum<<<cfg::Ff / 256, 256>>>();
    pack_a_f16<<<2048, 256>>>(x, axh, axl);
    pack_b_f16<<<4096, 256>>>(w_up, (uint2*)buh, (uint2*)bul);
    pack_w_down_f16<<<4096, 256>>>(w_down, (uint2*)dw);

    constexpr int SMEM1 = 3 * 4 * 8192;    // 98304 B
    constexpr int SMEM2 = 3 * 2 * 16384;   // 98304 B
    cudaFuncSetAttribute(tc_gemm1, cudaFuncAttributeMaxDynamicSharedMemorySize, SMEM1);
    cudaFuncSetAttribute(tc_gemm2, cudaFuncAttributeMaxDynamicSharedMemorySize, SMEM2);

    tc_gemm1<<<dim3(cfg::Ff / 128, cfg::M / 128), 256, SMEM1>>>(beta, Tptr);

    finalize_rpu<<<cfg::Ff / 256, 256>>>(rpu);

    tc_gemm2<<<dim3(cfg::Dd / 128, cfg::M / 128), 256, SMEM2>>>(ratep, dw, out);
}